// round 1
// baseline (speedup 1.0000x reference)
#include <cuda_runtime.h>
#include <cstdint>
#include <math.h>

// ============================================================================
// PlanCostEstimatorFull — fused per-batch kernel (fp32, round 0)
//
// Shapes: B=2048, N=64 nodes, M=63, conv chans 200->200->100->100(FEAT)
// Strategy: 1 CTA per batch. Gather-conv reassociated as dense GEMM
//   Y_k = W_k @ X  (k=0..2), then output-side gather:
//   out[o,m] = sum_k Y_k[o, idx[3(m-1)+k]] + b[o]   (m>=1; m==0 -> 0)
// LayerNorm (per-batch, over full OxN plane, ddof=1, eps on sd) fused.
// Gate/softmax/pool/MLP epilogues fused.
// ============================================================================

#define BATCH    2048
#define NNODES   64
#define NIDX     189      // 3*(N-1)

// smem layout (in floats)
//  bufA   : 0      .. 12800   (200*64)
//  bufB   : 12800  .. 25600   (200*64)
//  Wch    : 25600  .. 44800   (32 rows * 600 = 19200, raw conv-w chunk)
//  Ych    : 44800  .. 50944   (3*32*64 = 6144)
//  idxs   : 50944  .. 51136   (192 ints)
//  red    : 51136  .. 51200   (64)
//  gates  : 51200  .. 51264
//  alphas : 51264  .. 51328
//  comb   : 51328  .. 51528   (200)
//  z1s    : 51528  .. 51656   (128)
//  z2s    : 51656  .. 51720   (64)
#define SMEM_FLOATS 51720

extern __shared__ float smem[];

// ---------------------------------------------------------------------------
// One conv layer: Os[o*64+m] = gathered conv of Xs, optional LayerNorm+ReLU.
// CIN = input channels, COUT = output channels. 256 threads.
// Thread map for GEMM: olocal = t>>3 (0..31), cg = t&7 (8 cols each).
// ---------------------------------------------------------------------------
template<int CIN, int COUT, bool DO_LN>
__device__ __forceinline__ void conv_layer(
    const float* __restrict__ Xs, float* __restrict__ Os,
    float* __restrict__ Wch, float* __restrict__ Ych,
    const int* __restrict__ idxs, float* __restrict__ red,
    const float* __restrict__ wg, const float* __restrict__ bg)
{
    const int t = threadIdx.x;
    const int KC3 = CIN * 3;
    const int olocal = t >> 3;
    const int cg = t & 7;

    float s1 = 0.f, s2 = 0.f;

    for (int o0 = 0; o0 < COUT; o0 += 32) {
        const int OCa = (COUT - o0 < 32) ? (COUT - o0) : 32;

        // ---- stage raw weight chunk [o0 .. o0+OCa) x (CIN*3), coalesced ----
        {
            const float4* src = (const float4*)(wg + (size_t)o0 * KC3);
            float4* dst = (float4*)Wch;
            const int nv = OCa * KC3 / 4;
            for (int v = t; v < nv; v += 256) dst[v] = src[v];
        }
        __syncthreads();

        // ---- GEMM: Ych[k][olocal][c] = sum_i W[o,i,k] * X[i,c] ----
        if (olocal < OCa) {
            float a0[8], a1[8], a2[8];
            #pragma unroll
            for (int c = 0; c < 8; c++) { a0[c] = 0.f; a1[c] = 0.f; a2[c] = 0.f; }

            const float* wp = Wch + olocal * KC3;
            const float4* xv = ((const float4*)Xs) + cg * 2;

            #pragma unroll 2
            for (int i = 0; i < CIN; i++) {
                const float w0 = wp[0], w1 = wp[1], w2 = wp[2];
                wp += 3;
                const float4 xa = xv[0];
                const float4 xb = xv[1];
                xv += 16;
                a0[0] += w0 * xa.x; a0[1] += w0 * xa.y; a0[2] += w0 * xa.z; a0[3] += w0 * xa.w;
                a0[4] += w0 * xb.x; a0[5] += w0 * xb.y; a0[6] += w0 * xb.z; a0[7] += w0 * xb.w;
                a1[0] += w1 * xa.x; a1[1] += w1 * xa.y; a1[2] += w1 * xa.z; a1[3] += w1 * xa.w;
                a1[4] += w1 * xb.x; a1[5] += w1 * xb.y; a1[6] += w1 * xb.z; a1[7] += w1 * xb.w;
                a2[0] += w2 * xa.x; a2[1] += w2 * xa.y; a2[2] += w2 * xa.z; a2[3] += w2 * xa.w;
                a2[4] += w2 * xb.x; a2[5] += w2 * xb.y; a2[6] += w2 * xb.z; a2[7] += w2 * xb.w;
            }
            float4* y0 = (float4*)(Ych + (0 * 32 + olocal) * 64);
            float4* y1 = (float4*)(Ych + (1 * 32 + olocal) * 64);
            float4* y2 = (float4*)(Ych + (2 * 32 + olocal) * 64);
            y0[cg * 2]     = make_float4(a0[0], a0[1], a0[2], a0[3]);
            y0[cg * 2 + 1] = make_float4(a0[4], a0[5], a0[6], a0[7]);
            y1[cg * 2]     = make_float4(a1[0], a1[1], a1[2], a1[3]);
            y1[cg * 2 + 1] = make_float4(a1[4], a1[5], a1[6], a1[7]);
            y2[cg * 2]     = make_float4(a2[0], a2[1], a2[2], a2[3]);
            y2[cg * 2 + 1] = make_float4(a2[4], a2[5], a2[6], a2[7]);
        }
        __syncthreads();

        // ---- output-side gather + bias; m==0 stays zero ----
        for (int e = t; e < OCa * 64; e += 256) {
            const int ol = e >> 6;
            const int m  = e & 63;
            const int o  = o0 + ol;
            float v = 0.f;
            if (m != 0) {
                const int j3 = 3 * (m - 1);
                const int c0 = idxs[j3], c1 = idxs[j3 + 1], c2 = idxs[j3 + 2];
                v = Ych[ol * 64 + c0]
                  + Ych[(32 + ol) * 64 + c1]
                  + Ych[(64 + ol) * 64 + c2]
                  + __ldg(bg + o);
            }
            Os[o * 64 + m] = v;
            s1 += v;
            s2 += v * v;
        }
        __syncthreads();
    }

    if (DO_LN) {
        // block reduce s1, s2
        #pragma unroll
        for (int off = 16; off > 0; off >>= 1) {
            s1 += __shfl_down_sync(0xffffffffu, s1, off);
            s2 += __shfl_down_sync(0xffffffffu, s2, off);
        }
        const int wid = t >> 5, lid = t & 31;
        if (lid == 0) { red[wid] = s1; red[8 + wid] = s2; }
        __syncthreads();
        if (t == 0) {
            float S1 = 0.f, S2 = 0.f;
            #pragma unroll
            for (int w = 0; w < 8; w++) { S1 += red[w]; S2 += red[8 + w]; }
            const float n = (float)(COUT * 64);
            const float mu = S1 / n;
            float var = (S2 - S1 * mu) / (n - 1.f);
            var = fmaxf(var, 0.f);
            const float inv = 1.f / (sqrtf(var) + 1e-5f);
            red[16] = mu;
            red[17] = inv;
        }
        __syncthreads();
        const float mu = red[16], inv = red[17];
        for (int e = t; e < COUT * 64; e += 256) {
            const float v = (Os[e] - mu) * inv;
            Os[e] = fmaxf(v, 0.f);
        }
        __syncthreads();
    }
}

// ---------------------------------------------------------------------------
__global__ void __launch_bounds__(256)
plan_cost_kernel(
    const float* __restrict__ trees, const int* __restrict__ indexes,
    const unsigned char* __restrict__ maskp,
    const float* __restrict__ c1w, const float* __restrict__ c1b,
    const float* __restrict__ c2w, const float* __restrict__ c2b,
    const float* __restrict__ c3w, const float* __restrict__ c3b,
    const float* __restrict__ gw1, const float* __restrict__ gb1,
    const float* __restrict__ gw2, const float* __restrict__ gb2,
    const float* __restrict__ rw1, const float* __restrict__ rb1,
    const float* __restrict__ rw2, const float* __restrict__ rb2,
    const float* __restrict__ rw3, const float* __restrict__ rb3,
    float* __restrict__ out)
{
    const int b = blockIdx.x;
    const int t = threadIdx.x;

    float* bufA   = smem;
    float* bufB   = smem + 12800;
    float* Wch    = smem + 25600;
    float* Ych    = smem + 44800;
    int*   idxs   = (int*)(smem + 50944);
    float* red    = smem + 51136;
    float* gates  = smem + 51200;
    float* alphas = smem + 51264;
    float* comb   = smem + 51328;
    float* z1s    = smem + 51528;
    float* z2s    = smem + 51656;

    // ---- load batch inputs to smem ----
    {
        const float4* src = (const float4*)(trees + (size_t)b * 12800);
        float4* dst = (float4*)bufA;
        for (int v = t; v < 3200; v += 256) dst[v] = src[v];
        const int* isrc = indexes + (size_t)b * NIDX;
        for (int v = t; v < NIDX; v += 256) idxs[v] = isrc[v];
    }
    __syncthreads();

    // ---- conv stack ----
    conv_layer<200, 200, true >(bufA, bufB, Wch, Ych, idxs, red, c1w, c1b);
    conv_layer<200, 100, true >(bufB, bufA, Wch, Ych, idxs, red, c2w, c2b);
    conv_layer<100, 100, false>(bufA, bufB, Wch, Ych, idxs, red, c3w, c3b);
    const float* H3 = bufB;   // (100 feat) x (64 nodes), emb[n,f] = H3[f*64+n]

    const int wid = t >> 5, lid = t & 31;

    // ---- gate head: gate[n] = sum_h relu(emb[n]·w1[h] + b1[h]) * w2[h] + b2 ----
    for (int n = wid; n < 64; n += 8) {
        float acc1 = 0.f, acc2 = 0.f;
        const int h1 = lid;        // always < 50
        const int h2 = lid + 32;   // valid if < 50
        const float* w1p = gw1 + h1 * 100;
        const float* w2p = gw1 + h2 * 100;
        for (int f = 0; f < 100; f++) {
            const float e = H3[f * 64 + n];
            acc1 += e * __ldg(w1p + f);
            if (h2 < 50) acc2 += e * __ldg(w2p + f);
        }
        float contrib = fmaxf(acc1 + __ldg(gb1 + h1), 0.f) * __ldg(gw2 + h1);
        if (h2 < 50)
            contrib += fmaxf(acc2 + __ldg(gb1 + h2), 0.f) * __ldg(gw2 + h2);
        #pragma unroll
        for (int off = 16; off > 0; off >>= 1)
            contrib += __shfl_down_sync(0xffffffffu, contrib, off);
        if (lid == 0) {
            float gv = contrib + __ldg(gb2);
            if (maskp[(size_t)b * 64 + n]) gv = -INFINITY;
            gates[n] = gv;
        }
    }
    __syncthreads();

    // ---- softmax over 64 nodes (warp 0) ----
    if (wid == 0) {
        const float v1 = gates[lid], v2 = gates[lid + 32];
        float m = fmaxf(v1, v2);
        #pragma unroll
        for (int off = 16; off > 0; off >>= 1)
            m = fmaxf(m, __shfl_xor_sync(0xffffffffu, m, off));
        const float e1 = expf(v1 - m), e2 = expf(v2 - m);
        float s = e1 + e2;
        #pragma unroll
        for (int off = 16; off > 0; off >>= 1)
            s += __shfl_xor_sync(0xffffffffu, s, off);
        const float invs = 1.f / s;
        alphas[lid] = e1 * invs;
        alphas[lid + 32] = e2 * invs;
    }
    __syncthreads();

    // ---- pooled + root -> combined (also written to global) ----
    if (t < 100) {
        const float* row = H3 + t * 64;
        float acc = 0.f;
        #pragma unroll 4
        for (int n = 0; n < 64; n++) acc += alphas[n] * row[n];
        const float rootv = row[1];     // emb[:,1,:]
        comb[t] = rootv;
        comb[100 + t] = acc;
        out[BATCH + (size_t)b * 200 + t] = rootv;
        out[BATCH + (size_t)b * 200 + 100 + t] = acc;
    }
    __syncthreads();

    // ---- regressor MLP ----
    if (t < 128) {
        float acc = __ldg(rb1 + t);
        const float* wr = rw1 + t * 200;
        #pragma unroll 4
        for (int c = 0; c < 200; c++) acc += comb[c] * __ldg(wr + c);
        z1s[t] = fmaxf(acc, 0.f);
    }
    __syncthreads();
    if (t < 64) {
        float acc = __ldg(rb2 + t);
        const float* wr = rw2 + t * 128;
        #pragma unroll 4
        for (int c = 0; c < 128; c++) acc += z1s[c] * __ldg(wr + c);
        z2s[t] = fmaxf(acc, 0.f);
    }
    __syncthreads();
    if (wid == 0) {
        float acc = z2s[lid] * __ldg(rw3 + lid)
                  + z2s[lid + 32] * __ldg(rw3 + lid + 32);
        #pragma unroll
        for (int off = 16; off > 0; off >>= 1)
            acc += __shfl_down_sync(0xffffffffu, acc, off);
        if (lid == 0) out[b] = acc + __ldg(rb3);
    }
}

// ---------------------------------------------------------------------------
extern "C" void kernel_launch(void* const* d_in, const int* in_sizes, int n_in,
                              void* d_out, int out_size)
{
    (void)in_sizes; (void)n_in; (void)out_size;
    const size_t smem_bytes = (size_t)SMEM_FLOATS * sizeof(float);
    cudaFuncSetAttribute(plan_cost_kernel,
                         cudaFuncAttributeMaxDynamicSharedMemorySize,
                         (int)smem_bytes);

    plan_cost_kernel<<<BATCH, 256, smem_bytes>>>(
        (const float*)d_in[0],                 // trees
        (const int*)d_in[1],                   // indexes
        (const unsigned char*)d_in[2],         // mask_padding
        (const float*)d_in[3],  (const float*)d_in[4],   // conv1
        (const float*)d_in[5],  (const float*)d_in[6],   // conv2
        (const float*)d_in[7],  (const float*)d_in[8],   // conv3
        (const float*)d_in[9],  (const float*)d_in[10],  // gate_w1, gate_b1
        (const float*)d_in[11], (const float*)d_in[12],  // gate_w2, gate_b2
        (const float*)d_in[13], (const float*)d_in[14],  // reg_w1, reg_b1
        (const float*)d_in[15], (const float*)d_in[16],  // reg_w2, reg_b2
        (const float*)d_in[17], (const float*)d_in[18],  // reg_w3, reg_b3
        (float*)d_out);
}

// round 2
// speedup vs baseline: 1.1980x; 1.1980x over previous
#include <cuda_runtime.h>
#include <cstdint>
#include <math.h>

// ============================================================================
// PlanCostEstimatorFull — round 2
// 1 CTA per batch. Gather-conv as dense GEMM (Y_k = W_k @ X) + output gather.
// R2: 2rows x 8cols x 3taps register tile (48 acc), fma.rn.f32x2 packed FMA,
//     weights pre-padded to float4 (prep kernel) + cp.async double-buffering.
// ============================================================================

#define BATCH   2048
#define NIDX    189
#define IC      25          // i-chunk (K sub-tile) per staging step

typedef unsigned long long u64;

// padded weights: Wp[o*CIN + i] = (w0, w1, w2, 0)
__device__ float4 d_Wp1[200 * 200];
__device__ float4 d_Wp2[100 * 200];
__device__ float4 d_Wp3[100 * 100];

// smem layout (floats)
//  bufA 0..12800, bufB 12800..25600
//  Wch  25600..38400  (2 bufs x 64 rows x 25 x float4 = 12800 floats)
//  Ych  38400..50688  (3*64*64)
//  idx  50688..50880, red 50880..50944, gates 50944..51008,
//  alpha 51008..51072, comb 51072..51272, z1 51272..51400, z2 51400..51464
#define SMEM_FLOATS 51464

extern __shared__ float smem[];

__device__ __forceinline__ uint32_t smem_u32(const void* p) {
    return (uint32_t)__cvta_generic_to_shared(p);
}

#define CP_COMMIT()  asm volatile("cp.async.commit_group;")
#define CP_WAIT(n)   asm volatile("cp.async.wait_group %0;" :: "n"(n))
#define PK(d, f)     asm("mov.b64 %0, {%1, %1};" : "=l"(d) : "r"(__float_as_uint(f)))
#define FFMA2(d,a,b) asm("fma.rn.f32x2 %0, %1, %2, %0;" : "+l"(d) : "l"(a), "l"(b))

// stage [rows x IC] float4 weight chunk into smem (contiguous) via cp.async
__device__ __forceinline__ void stage_wchunk(uint32_t dst_u32,
                                             const float4* __restrict__ src,
                                             int cin, int rows, int t)
{
    for (int e = t; e < rows * IC; e += 256) {
        const int r = e / IC;
        const int s = e - r * IC;
        const uint32_t d = dst_u32 + (uint32_t)e * 16u;
        const float4* sp = src + r * cin + s;
        asm volatile("cp.async.cg.shared.global [%0], [%1], 16;" :: "r"(d), "l"(sp));
    }
}

// ---------------------------------------------------------------------------
template<int CIN, int COUT, bool DO_LN>
__device__ __forceinline__ void conv_layer(
    const float* __restrict__ Xs, float* __restrict__ Os,
    float* __restrict__ Wch, float* __restrict__ Ych,
    const int* __restrict__ idxs, float* __restrict__ red,
    const float4* __restrict__ Wp, const float* __restrict__ bg)
{
    const int t = threadIdx.x;
    const int cg = t & 7;               // column group: 8 cols each
    const int rowl = (t >> 3) * 2;      // local row pair base (0..62)
    const uint32_t wch_u32 = smem_u32(Wch);
    constexpr int NC = CIN / IC;        // i-chunks

    float s1 = 0.f, s2 = 0.f;

    for (int o0 = 0; o0 < COUT; o0 += 64) {
        const int rows = (COUT - o0 < 64) ? (COUT - o0) : 64;   // 64, 8 or 36 (even)
        const bool active = rowl < rows;

        u64 acc[6][4];
        #pragma unroll
        for (int j = 0; j < 6; j++)
            #pragma unroll
            for (int p = 0; p < 4; p++) acc[j][p] = 0ull;

        // prefetch first weight chunk
        stage_wchunk(wch_u32, Wp + o0 * CIN, CIN, rows, t);
        CP_COMMIT();

        for (int ic = 0; ic < NC; ic++) {
            if (ic + 1 < NC) {
                stage_wchunk(wch_u32 + ((ic + 1) & 1) * 25600u,
                             Wp + o0 * CIN + (ic + 1) * IC, CIN, rows, t);
                CP_COMMIT();
                CP_WAIT(1);
            } else {
                CP_WAIT(0);
            }
            __syncthreads();

            if (active) {
                const float4* wb = (const float4*)Wch + (ic & 1) * 1600 + rowl * IC;
                const float*   xb = Xs + ic * IC * 64 + cg * 8;

                #pragma unroll 5
                for (int ii = 0; ii < IC; ii++) {
                    const float4 wA = wb[ii];
                    const float4 wB = wb[IC + ii];
                    const ulonglong2 xv0 = *(const ulonglong2*)(xb + ii * 64);
                    const ulonglong2 xv1 = *(const ulonglong2*)(xb + ii * 64 + 4);
                    const u64 X0 = xv0.x, X1 = xv0.y, X2 = xv1.x, X3 = xv1.y;

                    u64 w0, w1, w2, w3, w4, w5;
                    PK(w0, wA.x); PK(w1, wA.y); PK(w2, wA.z);
                    PK(w3, wB.x); PK(w4, wB.y); PK(w5, wB.z);

                    FFMA2(acc[0][0], w0, X0); FFMA2(acc[0][1], w0, X1);
                    FFMA2(acc[0][2], w0, X2); FFMA2(acc[0][3], w0, X3);
                    FFMA2(acc[1][0], w1, X0); FFMA2(acc[1][1], w1, X1);
                    FFMA2(acc[1][2], w1, X2); FFMA2(acc[1][3], w1, X3);
                    FFMA2(acc[2][0], w2, X0); FFMA2(acc[2][1], w2, X1);
                    FFMA2(acc[2][2], w2, X2); FFMA2(acc[2][3], w2, X3);
                    FFMA2(acc[3][0], w3, X0); FFMA2(acc[3][1], w3, X1);
                    FFMA2(acc[3][2], w3, X2); FFMA2(acc[3][3], w3, X3);
                    FFMA2(acc[4][0], w4, X0); FFMA2(acc[4][1], w4, X1);
                    FFMA2(acc[4][2], w4, X2); FFMA2(acc[4][3], w4, X3);
                    FFMA2(acc[5][0], w5, X0); FFMA2(acc[5][1], w5, X1);
                    FFMA2(acc[5][2], w5, X2); FFMA2(acc[5][3], w5, X3);
                }
            }
            __syncthreads();
        }

        // write Y tiles: Ych[k][rowlocal][col]
        if (active) {
            #pragma unroll
            for (int r = 0; r < 2; r++)
                #pragma unroll
                for (int k = 0; k < 3; k++) {
                    ulonglong2* d = (ulonglong2*)(Ych + (k * 64 + rowl + r) * 64 + cg * 8);
                    d[0] = make_ulonglong2(acc[r * 3 + k][0], acc[r * 3 + k][1]);
                    d[1] = make_ulonglong2(acc[r * 3 + k][2], acc[r * 3 + k][3]);
                }
        }
        __syncthreads();

        // output-side gather + bias; m==0 stays zero
        for (int e = t; e < rows * 64; e += 256) {
            const int ol = e >> 6;
            const int m  = e & 63;
            float v = 0.f;
            if (m != 0) {
                const int j3 = 3 * (m - 1);
                v = Ych[ol * 64 + idxs[j3]]
                  + Ych[(64 + ol) * 64 + idxs[j3 + 1]]
                  + Ych[(128 + ol) * 64 + idxs[j3 + 2]]
                  + __ldg(bg + o0 + ol);
            }
            Os[(o0 + ol) * 64 + m] = v;
            s1 += v;
            s2 += v * v;
        }
        __syncthreads();
    }

    if (DO_LN) {
        #pragma unroll
        for (int off = 16; off > 0; off >>= 1) {
            s1 += __shfl_down_sync(0xffffffffu, s1, off);
            s2 += __shfl_down_sync(0xffffffffu, s2, off);
        }
        const int wid = t >> 5, lid = t & 31;
        if (lid == 0) { red[wid] = s1; red[8 + wid] = s2; }
        __syncthreads();
        if (t == 0) {
            float S1 = 0.f, S2 = 0.f;
            #pragma unroll
            for (int w = 0; w < 8; w++) { S1 += red[w]; S2 += red[8 + w]; }
            const float n = (float)(COUT * 64);
            const float mu = S1 / n;
            float var = (S2 - S1 * mu) / (n - 1.f);
            var = fmaxf(var, 0.f);
            red[16] = mu;
            red[17] = 1.f / (sqrtf(var) + 1e-5f);
        }
        __syncthreads();
        const float mu = red[16], inv = red[17];
        for (int e = t; e < COUT * 64; e += 256) {
            const float v = (Os[e] - mu) * inv;
            Os[e] = fmaxf(v, 0.f);
        }
        __syncthreads();
    }
}

// ---------------------------------------------------------------------------
__global__ void prep_weights(const float* __restrict__ c1w,
                             const float* __restrict__ c2w,
                             const float* __restrict__ c3w)
{
    const int idx = blockIdx.x * blockDim.x + threadIdx.x;
    if (idx < 40000) {
        const float* s = c1w + idx * 3;
        d_Wp1[idx] = make_float4(s[0], s[1], s[2], 0.f);
    } else if (idx < 60000) {
        const int j = idx - 40000;
        const float* s = c2w + j * 3;
        d_Wp2[j] = make_float4(s[0], s[1], s[2], 0.f);
    } else if (idx < 70000) {
        const int j = idx - 60000;
        const float* s = c3w + j * 3;
        d_Wp3[j] = make_float4(s[0], s[1], s[2], 0.f);
    }
}

// ---------------------------------------------------------------------------
__global__ void __launch_bounds__(256)
plan_cost_kernel(
    const float* __restrict__ trees, const int* __restrict__ indexes,
    const unsigned char* __restrict__ maskp,
    const float* __restrict__ c1b, const float* __restrict__ c2b,
    const float* __restrict__ c3b,
    const float* __restrict__ gw1, const float* __restrict__ gb1,
    const float* __restrict__ gw2, const float* __restrict__ gb2,
    const float* __restrict__ rw1, const float* __restrict__ rb1,
    const float* __restrict__ rw2, const float* __restrict__ rb2,
    const float* __restrict__ rw3, const float* __restrict__ rb3,
    float* __restrict__ out)
{
    const int b = blockIdx.x;
    const int t = threadIdx.x;

    float* bufA   = smem;
    float* bufB   = smem + 12800;
    float* Wch    = smem + 25600;
    float* Ych    = smem + 38400;
    int*   idxs   = (int*)(smem + 50688);
    float* red    = smem + 50880;
    float* gates  = smem + 50944;
    float* alphas = smem + 51008;
    float* comb   = smem + 51072;
    float* z1s    = smem + 51272;
    float* z2s    = smem + 51400;

    // load batch inputs
    {
        const float4* src = (const float4*)(trees + (size_t)b * 12800);
        float4* dst = (float4*)bufA;
        for (int v = t; v < 3200; v += 256) dst[v] = src[v];
        const int* isrc = indexes + (size_t)b * NIDX;
        for (int v = t; v < NIDX; v += 256) idxs[v] = isrc[v];
    }
    __syncthreads();

    conv_layer<200, 200, true >(bufA, bufB, Wch, Ych, idxs, red, d_Wp1, c1b);
    conv_layer<200, 100, true >(bufB, bufA, Wch, Ych, idxs, red, d_Wp2, c2b);
    conv_layer<100, 100, false>(bufA, bufB, Wch, Ych, idxs, red, d_Wp3, c3b);
    const float* H3 = bufB;     // emb[n,f] = H3[f*64 + n]

    const int wid = t >> 5, lid = t & 31;

    // gate head
    for (int n = wid; n < 64; n += 8) {
        float acc1 = 0.f, acc2 = 0.f;
        const int h1 = lid;
        const int h2 = lid + 32;
        const float* w1p = gw1 + h1 * 100;
        const float* w2p = gw1 + h2 * 100;
        for (int f = 0; f < 100; f++) {
            const float e = H3[f * 64 + n];
            acc1 += e * __ldg(w1p + f);
            if (h2 < 50) acc2 += e * __ldg(w2p + f);
        }
        float contrib = fmaxf(acc1 + __ldg(gb1 + h1), 0.f) * __ldg(gw2 + h1);
        if (h2 < 50)
            contrib += fmaxf(acc2 + __ldg(gb1 + h2), 0.f) * __ldg(gw2 + h2);
        #pragma unroll
        for (int off = 16; off > 0; off >>= 1)
            contrib += __shfl_down_sync(0xffffffffu, contrib, off);
        if (lid == 0) {
            float gv = contrib + __ldg(gb2);
            if (maskp[(size_t)b * 64 + n]) gv = -INFINITY;
            gates[n] = gv;
        }
    }
    __syncthreads();

    // softmax (warp 0)
    if (wid == 0) {
        const float v1 = gates[lid], v2 = gates[lid + 32];
        float m = fmaxf(v1, v2);
        #pragma unroll
        for (int off = 16; off > 0; off >>= 1)
            m = fmaxf(m, __shfl_xor_sync(0xffffffffu, m, off));
        const float e1 = expf(v1 - m), e2 = expf(v2 - m);
        float s = e1 + e2;
        #pragma unroll
        for (int off = 16; off > 0; off >>= 1)
            s += __shfl_xor_sync(0xffffffffu, s, off);
        const float invs = 1.f / s;
        alphas[lid] = e1 * invs;
        alphas[lid + 32] = e2 * invs;
    }
    __syncthreads();

    // pooled + root -> combined
    if (t < 100) {
        const float* row = H3 + t * 64;
        float acc = 0.f;
        #pragma unroll 4
        for (int n = 0; n < 64; n++) acc += alphas[n] * row[n];
        const float rootv = row[1];
        comb[t] = rootv;
        comb[100 + t] = acc;
        out[BATCH + (size_t)b * 200 + t] = rootv;
        out[BATCH + (size_t)b * 200 + 100 + t] = acc;
    }
    __syncthreads();

    // regressor MLP
    if (t < 128) {
        float acc = __ldg(rb1 + t);
        const float* wr = rw1 + t * 200;
        #pragma unroll 4
        for (int c = 0; c < 200; c++) acc += comb[c] * __ldg(wr + c);
        z1s[t] = fmaxf(acc, 0.f);
    }
    __syncthreads();
    if (t < 64) {
        float acc = __ldg(rb2 + t);
        const float* wr = rw2 + t * 128;
        #pragma unroll 4
        for (int c = 0; c < 128; c++) acc += z1s[c] * __ldg(wr + c);
        z2s[t] = fmaxf(acc, 0.f);
    }
    __syncthreads();
    if (wid == 0) {
        float acc = z2s[lid] * __ldg(rw3 + lid)
                  + z2s[lid + 32] * __ldg(rw3 + lid + 32);
        #pragma unroll
        for (int off = 16; off > 0; off >>= 1)
            acc += __shfl_down_sync(0xffffffffu, acc, off);
        if (lid == 0) out[b] = acc + __ldg(rb3);
    }
}

// ---------------------------------------------------------------------------
extern "C" void kernel_launch(void* const* d_in, const int* in_sizes, int n_in,
                              void* d_out, int out_size)
{
    (void)in_sizes; (void)n_in; (void)out_size;
    const size_t smem_bytes = (size_t)SMEM_FLOATS * sizeof(float);
    cudaFuncSetAttribute(plan_cost_kernel,
                         cudaFuncAttributeMaxDynamicSharedMemorySize,
                         (int)smem_bytes);

    prep_weights<<<(70000 + 255) / 256, 256>>>(
        (const float*)d_in[3], (const float*)d_in[5], (const float*)d_in[7]);

    plan_cost_kernel<<<BATCH, 256, smem_bytes>>>(
        (const float*)d_in[0],
        (const int*)d_in[1],
        (const unsigned char*)d_in[2],
        (const float*)d_in[4],                     // conv1_b
        (const float*)d_in[6],                     // conv2_b
        (const float*)d_in[8],                     // conv3_b
        (const float*)d_in[9],  (const float*)d_in[10],
        (const float*)d_in[11], (const float*)d_in[12],
        (const float*)d_in[13], (const float*)d_in[14],
        (const float*)d_in[15], (const float*)d_in[16],
        (const float*)d_in[17], (const float*)d_in[18],
        (float*)d_out);
}

// round 5
// speedup vs baseline: 1.2709x; 1.0609x over previous
#include <cuda_runtime.h>
#include <cstdint>
#include <math.h>

// ============================================================================
// PlanCostEstimatorFull — round 3: tensor cores (mma.sync m16n8k8 tf32 x3)
//
// Per batch (1 CTA, 512 thr): conv as GEMM  Y[r=3o+k, m] = W'[r,:] @ X[:, m]
//   A (weights) pre-split hi/lo into fragment-ready float4 globals (prep kernel)
//   B (activations) fragment-major hi/lo planes in smem
//   3-term tf32 split: D += Ah*Bh + Al*Bh + Ah*Bl  (error ~2^-22)
// Chunked epilogue: 240 rows (80 outputs) per chunk -> Ych smem, gather+bias,
// LayerNorm fused into hi/lo split pass. Gate/softmax/pool/MLP as before.
// ============================================================================

#define BATCH 2048
#define NT    512
#define NIDX  189

#define T1  38
#define KS1 25
#define T2  19
#define KS2 25
#define T3  19
#define KS3 13

#define N1 (T1*KS1*32)   // 30400
#define N2 (T2*KS2*32)   // 15200
#define N3 (T3*KS3*32)   // 7904

__device__ uint4 g_A1h[N1], g_A1l[N1];
__device__ uint4 g_A2h[N2], g_A2l[N2];
__device__ uint4 g_A3h[N3], g_A3l[N3];

// smem offsets (floats)
#define XF_HI   0
#define XF_LO   12800
#define XBUF    25600
#define YCH     38400
#define YSTR    68
#define S_IDX   54720   /* 192 ints */
#define S_RED   54912   /* 40 */
#define S_GATES 54952
#define S_ALPHA 55016
#define S_COMB  55080
#define S_Z1    55280
#define S_Z2    55408
#define SMEM_FLOATS 55480

extern __shared__ float smem[];

__device__ __forceinline__ uint32_t f2tf32(float f) {
    uint32_t u;
    asm("cvt.rna.tf32.f32 %0, %1;" : "=r"(u) : "f"(f));
    return u;
}

// fragment-major activation address: input channel i, node m
__device__ __forceinline__ int xf_addr(int i, int m) {
    return ((i >> 3) * 32 + ((m & 7) * 4 | (i & 3))) * 16
         + (((i >> 2) & 1) << 3) + (m >> 3);
}

__device__ __forceinline__ void split_store(float v, int addr) {
    const uint32_t h = f2tf32(v);
    const float hf = __uint_as_float(h);
    const uint32_t l = f2tf32(v - hf);
    smem[XF_HI + addr] = hf;
    smem[XF_LO + addr] = __uint_as_float(l);
}

#define MMA(d, a, b0, b1)                                                     \
    asm volatile("mma.sync.aligned.m16n8k8.row.col.f32.tf32.tf32.f32 "        \
        "{%0,%1,%2,%3},{%4,%5,%6,%7},{%8,%9},{%0,%1,%2,%3};"                  \
        : "+f"(d[0]), "+f"(d[1]), "+f"(d[2]), "+f"(d[3])                      \
        : "r"((a).x), "r"((a).y), "r"((a).z), "r"((a).w), "r"(b0), "r"(b1))

#define MMA3(J, B0H, B1H, B0L, B1L)         \
    MMA(acc[J], ah, B0H, B1H);              \
    MMA(acc[J], al, B0H, B1H);              \
    MMA(acc[J], ah, B0L, B1L)

// ---------------------------------------------------------------------------
// One conv layer pass. TILES m16 tiles, KS k-steps, COUT output channels.
// ---------------------------------------------------------------------------
template<int TILES, int KS, int COUT, bool LN, bool PADK>
__device__ __forceinline__ void conv_pass(
    const uint4* __restrict__ Ah, const uint4* __restrict__ Al,
    const float* __restrict__ bias, const int* __restrict__ idxs)
{
    const int t = threadIdx.x;
    const int wid = t >> 5, lane = t & 31;
    const int gid = lane >> 2, tid4 = lane & 3;

    float s1 = 0.f, s2 = 0.f;

    for (int tb = 0; tb < TILES; tb += 15) {
        const int T = tb + wid;
        if (wid < 15 && T < TILES) {
            float acc[8][4];
            #pragma unroll
            for (int j = 0; j < 8; j++)
                #pragma unroll
                for (int p = 0; p < 4; p++) acc[j][p] = 0.f;

            const uint4* A0h = Ah + (size_t)T * KS * 32 + lane;
            const uint4* A0l = Al + (size_t)T * KS * 32 + lane;
            uint4 ah = __ldg(A0h);
            uint4 al = __ldg(A0l);

            for (int s = 0; s < KS; s++) {
                const int sn = (s + 1 < KS) ? s + 1 : s;
                const uint4 ahn = __ldg(A0h + sn * 32);
                const uint4 aln = __ldg(A0l + sn * 32);

                const uint4* bhp = (const uint4*)&smem[XF_HI + s * 512 + lane * 16];
                const uint4* blp = (const uint4*)&smem[XF_LO + s * 512 + lane * 16];
                const uint4 h0 = bhp[0], h1 = bhp[1], h2 = bhp[2], h3 = bhp[3];
                const uint4 L0 = blp[0], L1 = blp[1], L2 = blp[2], L3 = blp[3];

                MMA3(0, h0.x, h2.x, L0.x, L2.x);
                MMA3(1, h0.y, h2.y, L0.y, L2.y);
                MMA3(2, h0.z, h2.z, L0.z, L2.z);
                MMA3(3, h0.w, h2.w, L0.w, L2.w);
                MMA3(4, h1.x, h3.x, L1.x, L3.x);
                MMA3(5, h1.y, h3.y, L1.y, L3.y);
                MMA3(6, h1.z, h3.z, L1.z, L3.z);
                MMA3(7, h1.w, h3.w, L1.w, L3.w);

                ah = ahn;
                al = aln;
            }

            // write D frags to Ych (local rows, padded stride)
            const int lr = (T - tb) * 16 + gid;
            float* y0 = &smem[YCH + lr * YSTR + 2 * tid4];
            float* y1 = y0 + 8 * YSTR;
            #pragma unroll
            for (int j = 0; j < 8; j++) {
                *(float2*)(y0 + 8 * j) = make_float2(acc[j][0], acc[j][1]);
                *(float2*)(y1 + 8 * j) = make_float2(acc[j][2], acc[j][3]);
            }
        }
        __syncthreads();

        // gather + bias for outputs covered by this chunk
        const int o0 = (tb * 16) / 3;
        const int no = (COUT - o0 < 80) ? (COUT - o0) : 80;
        for (int e = t; e < no * 64; e += NT) {
            const int ol = e >> 6;
            const int m  = e & 63;
            float v = 0.f;
            if (m != 0) {
                const int j3 = 3 * (m - 1);
                v = smem[YCH + (3 * ol    ) * YSTR + idxs[j3]]
                  + smem[YCH + (3 * ol + 1) * YSTR + idxs[j3 + 1]]
                  + smem[YCH + (3 * ol + 2) * YSTR + idxs[j3 + 2]]
                  + __ldg(bias + o0 + ol);
            }
            smem[XBUF + (o0 + ol) * 64 + m] = v;
            if (LN) { s1 += v; s2 += v * v; }
        }
        __syncthreads();
    }

    if (LN) {
        #pragma unroll
        for (int off = 16; off > 0; off >>= 1) {
            s1 += __shfl_down_sync(0xffffffffu, s1, off);
            s2 += __shfl_down_sync(0xffffffffu, s2, off);
        }
        if (lane == 0) { smem[S_RED + wid] = s1; smem[S_RED + 16 + wid] = s2; }
        __syncthreads();
        if (t == 0) {
            float S1 = 0.f, S2 = 0.f;
            #pragma unroll
            for (int w = 0; w < 16; w++) { S1 += smem[S_RED + w]; S2 += smem[S_RED + 16 + w]; }
            const float n = (float)(COUT * 64);
            const float mu = S1 / n;
            float var = (S2 - S1 * mu) / (n - 1.f);
            var = fmaxf(var, 0.f);
            smem[S_RED + 32] = mu;
            smem[S_RED + 33] = 1.f / (sqrtf(var) + 1e-5f);
        }
        __syncthreads();
        const float mu = smem[S_RED + 32], inv = smem[S_RED + 33];
        // LN + relu + tf32 hi/lo split into fragment-major layout
        for (int e = t; e < COUT * 64; e += NT) {
            const float v = fmaxf((smem[XBUF + e] - mu) * inv, 0.f);
            split_store(v, xf_addr(e >> 6, e & 63));
        }
        if (PADK) {
            for (int e = t; e < 4 * 64; e += NT) {
                const int a = xf_addr(COUT + (e >> 6), e & 63);
                smem[XF_HI + a] = 0.f;
                smem[XF_LO + a] = 0.f;
            }
        }
        __syncthreads();
    }
}

// ---------------------------------------------------------------------------
// Prep: build fragment-ready hi/lo A planes for all 3 conv layers.
// Frag order (m16n8k8 row-major A): a0=A[g][c], a1=A[g+8][c], a2=A[g][c+4],
// a3=A[g+8][c+4]  (g = lane>>2, c = ks*8 + (lane&3)).
// ---------------------------------------------------------------------------
__device__ __forceinline__ float wget(const float* w, int COUT, int CIN, int r, int c) {
    if (r < 3 * COUT && c < CIN) {
        const int o = r / 3, k = r - o * 3;
        return w[(o * CIN + c) * 3 + k];
    }
    return 0.f;
}

__device__ __forceinline__ void prep_frag(const float* __restrict__ w,
    int COUT, int CIN, int KS, int f, uint4* __restrict__ Ah, uint4* __restrict__ Al)
{
    const int T = f / (KS * 32);
    const int rem = f - T * KS * 32;
    const int s = rem >> 5;
    const int l = rem & 31;
    const int gid = l >> 2, tid4 = l & 3;
    const int r0 = T * 16 + gid;
    const int c0 = s * 8 + tid4;

    const float v[4] = { wget(w, COUT, CIN, r0,     c0),
                         wget(w, COUT, CIN, r0 + 8, c0),
                         wget(w, COUT, CIN, r0,     c0 + 4),
                         wget(w, COUT, CIN, r0 + 8, c0 + 4) };
    uint32_t hi[4], lo[4];
    #pragma unroll
    for (int i = 0; i < 4; i++) {
        hi[i] = f2tf32(v[i]);
        lo[i] = f2tf32(v[i] - __uint_as_float(hi[i]));
    }
    Ah[f] = make_uint4(hi[0], hi[1], hi[2], hi[3]);
    Al[f] = make_uint4(lo[0], lo[1], lo[2], lo[3]);
}

__global__ void prep_weights(const float* __restrict__ c1w,
                             const float* __restrict__ c2w,
                             const float* __restrict__ c3w)
{
    const int f = blockIdx.x * 256 + threadIdx.x;
    if (f < N1)                prep_frag(c1w, 200, 200, KS1, f,            g_A1h, g_A1l);
    else if (f < N1 + N2)      prep_frag(c2w, 100, 200, KS2, f - N1,       g_A2h, g_A2l);
    else if (f < N1 + N2 + N3) prep_frag(c3w, 100, 100, KS3, f - N1 - N2,  g_A3h, g_A3l);
}

// ---------------------------------------------------------------------------
__global__ void __launch_bounds__(NT)
plan_cost_kernel(
    const float* __restrict__ trees, const int* __restrict__ indexes,
    const unsigned char* __restrict__ maskp,
    const float* __restrict__ c1b, const float* __restrict__ c2b,
    const float* __restrict__ c3b,
    const float* __restrict__ gw1, const float* __restrict__ gb1,
    const float* __restrict__ gw2, const float* __restrict__ gb2,
    const float* __restrict__ rw1, const float* __restrict__ rb1,
    const float* __restrict__ rw2, const float* __restrict__ rb2,
    const float* __restrict__ rw3, const float* __restrict__ rb3,
    float* __restrict__ out)
{
    const int b = blockIdx.x;
    const int t = threadIdx.x;
    int* idxs = (int*)&smem[S_IDX];

    // load indexes + trees (split hi/lo into fragment-major layout)
    {
        const int* isrc = indexes + (size_t)b * NIDX;
        for (int v = t; v < NIDX; v += NT) idxs[v] = isrc[v];
        const float* tb_ = trees + (size_t)b * 12800;
        for (int e = t; e < 12800; e += NT)
            split_store(tb_[e], xf_addr(e >> 6, e & 63));
    }
    __syncthreads();

    conv_pass<T1, KS1, 200, true,  false>(g_A1h, g_A1l, c1b, idxs);
    conv_pass<T2, KS2, 100, true,  true >(g_A2h, g_A2l, c2b, idxs);
    conv_pass<T3, KS3, 100, false, false>(g_A3h, g_A3l, c3b, idxs);

    const float* H3 = &smem[XBUF];     // emb[n,f] = H3[f*64 + n]
    float* gates  = &smem[S_GATES];
    float* alphas = &smem[S_ALPHA];
    float* comb   = &smem[S_COMB];
    float* z1s    = &smem[S_Z1];
    float* z2s    = &smem[S_Z2];
    const int wid = t >> 5, lid = t & 31;

    // gate head
    for (int n = wid; n < 64; n += 16) {
        float acc1 = 0.f, acc2 = 0.f;
        const int h1 = lid;
        const int h2 = lid + 32;
        const float* w1p = gw1 + h1 * 100;
        const float* w2p = gw1 + h2 * 100;
        for (int f = 0; f < 100; f++) {
            const float e = H3[f * 64 + n];
            acc1 += e * __ldg(w1p + f);
            if (h2 < 50) acc2 += e * __ldg(w2p + f);
        }
        float contrib = fmaxf(acc1 + __ldg(gb1 + h1), 0.f) * __ldg(gw2 + h1);
        if (h2 < 50)
            contrib += fmaxf(acc2 + __ldg(gb1 + h2), 0.f) * __ldg(gw2 + h2);
        #pragma unroll
        for (int off = 16; off > 0; off >>= 1)
            contrib += __shfl_down_sync(0xffffffffu, contrib, off);
        if (lid == 0) {
            float gv = contrib + __ldg(gb2);
            if (maskp[(size_t)b * 64 + n]) gv = -INFINITY;
            gates[n] = gv;
        }
    }
    __syncthreads();

    // softmax over 64 nodes (warp 0)
    if (wid == 0) {
        const float v1 = gates[lid], v2 = gates[lid + 32];
        float m = fmaxf(v1, v2);
        #pragma unroll
        for (int off = 16; off > 0; off >>= 1)
            m = fmaxf(m, __shfl_xor_sync(0xffffffffu, m, off));
        const float e1 = expf(v1 - m), e2 = expf(v2 - m);
        float s = e1 + e2;
        #pragma unroll
        for (int off = 16; off > 0; off >>= 1)
            s += __shfl_xor_sync(0xffffffffu, s, off);
        const float invs = 1.f / s;
        alphas[lid] = e1 * invs;
        alphas[lid + 32] = e2 * invs;
    }
    __syncthreads();

    // pooled + root -> combined
    if (t < 100) {
        const float* row = H3 + t * 64;
        float acc = 0.f;
        #pragma unroll 4
        for (int n = 0; n < 64; n++) acc += alphas[n] * row[n];
        const float rootv = row[1];
        comb[t] = rootv;
        comb[100 + t] = acc;
        out[BATCH + (size_t)b * 200 + t] = rootv;
        out[BATCH + (size_t)b * 200 + 100 + t] = acc;
    }
    __syncthreads();

    // regressor MLP
    if (t < 128) {
        float acc = __ldg(rb1 + t);
        const float* wr = rw1 + t * 200;
        #pragma unroll 4
        for (int c = 0; c < 200; c++) acc += comb[c] * __ldg(wr + c);
        z1s[t] = fmaxf(acc, 0.f);
    }
    __syncthreads();
    if (t < 64) {
        float acc = __ldg(rb2 + t);
        const float* wr = rw2 + t * 128;
        #pragma unroll 4
        for (int c = 0; c < 128; c++) acc += z1s[c] * __ldg(wr + c);
        z2s[t] = fmaxf(acc, 0.f);
    }
    __syncthreads();
    if (wid == 0) {
        float acc = z2s[lid] * __ldg(rw3 + lid)
                  + z2s[lid + 32] * __ldg(rw3 + lid + 32);
        #pragma unroll
        for (int off = 16; off > 0; off >>= 1)
            acc += __shfl_down_sync(0xffffffffu, acc, off);
        if (lid == 0) out[b] = acc + __ldg(rb3);
    }
}

// ---------------------------------------------------------------------------
extern "C" void kernel_launch(void* const* d_in, const int* in_sizes, int n_in,
                              void* d_out, int out_size)
{
    (void)in_sizes; (void)n_in; (void)out_size;
    const size_t smem_bytes = (size_t)SMEM_FLOATS * sizeof(float);
    cudaFuncSetAttribute(plan_cost_kernel,
                         cudaFuncAttributeMaxDynamicSharedMemorySize,
                         (int)smem_bytes);

    prep_weights<<<(N1 + N2 + N3 + 255) / 256, 256>>>(
        (const float*)d_in[3], (const float*)d_in[5], (const float*)d_in[7]);

    plan_cost_kernel<<<BATCH, NT, smem_bytes>>>(
        (const float*)d_in[0],
        (const int*)d_in[1],
        (const unsigned char*)d_in[2],
        (const float*)d_in[4],
        (const float*)d_in[6],
        (const float*)d_in[8],
        (const float*)d_in[9],  (const float*)d_in[10],
        (const float*)d_in[11], (const float*)d_in[12],
        (const float*)d_in[13], (const float*)d_in[14],
        (const float*)d_in[15], (const float*)d_in[16],
        (const float*)d_in[17], (const float*)d_in[18],
        (float*)d_out);
}

// round 9
// speedup vs baseline: 1.6075x; 1.2649x over previous
#include <cuda_runtime.h>
#include <cstdint>
#include <math.h>

// ============================================================================
// PlanCostEstimatorFull — round 9 (identical to round 7; round-8 bench was an
// infra failure, re-benching the same kernel)
// tf32x3 mma.sync tensor-core conv stack, per-batch CTA (384 thr, 12 warps).
// (1) swizzled B-fragment layout -> conflict-free LDS.128
// (2) 8 MMA warps x 2 M-tiles per B load (B smem traffic halved)
// (3) B loaded in hi/lo halves to cap register pressure
// ============================================================================

#define BATCH 2048
#define NT    384
#define NW    12
#define NIDX  189

#define TIL1  38
#define KS1   25
#define TIL2  19
#define KS2   25
#define TIL3  19
#define KS3   13

#define N1 (TIL1*KS1*32)   // 30400
#define N2 (TIL2*KS2*32)   // 15200
#define N3 (TIL3*KS3*32)   // 7904

__device__ uint4 g_A1h[N1], g_A1l[N1];
__device__ uint4 g_A2h[N2], g_A2l[N2];
__device__ uint4 g_A3h[N3], g_A3l[N3];

// smem offsets (floats)
#define XF_HI   0
#define XF_LO   12800
#define XBUF    25600
#define YCH     38400
#define YSTR    68
#define S_IDX   54720   /* 192 ints */
#define S_RED   54912   /* 40 */
#define S_GATES 54952
#define S_ALPHA 55016
#define S_COMB  55080
#define S_Z1    55280
#define S_Z2    55408
#define SMEM_FLOATS 55480

extern __shared__ float smem[];

__device__ __forceinline__ uint32_t f2tf32(float f) {
    uint32_t u;
    asm("cvt.rna.tf32.f32 %0, %1;" : "=r"(u) : "f"(f));
    return u;
}

// fragment-major activation address with chunk swizzle (conflict-free reads):
// block (=lane within k-step) b, 16-float payload split in 4 chunks; logical
// chunk c stored at physical slot (c + (b>>1)) & 3.
__device__ __forceinline__ int xf_addr(int i, int m) {
    const int blk = (i >> 3) * 32 + ((m & 7) * 4 | (i & 3));
    const int off = (((i >> 2) & 1) << 3) + (m >> 3);       // 0..15
    const int c   = off >> 2;
    const int w   = off & 3;
    const int rot = (blk >> 1) & 3;                          // == (lane>>1)&3
    return blk * 16 + (((c + rot) & 3) << 2) + w;
}

__device__ __forceinline__ void split_store(float v, int addr) {
    const uint32_t h = f2tf32(v);
    const float hf = __uint_as_float(h);
    const uint32_t l = f2tf32(v - hf);
    smem[XF_HI + addr] = hf;
    smem[XF_LO + addr] = __uint_as_float(l);
}

#define MMA(d, a, b0, b1)                                                     \
    asm volatile("mma.sync.aligned.m16n8k8.row.col.f32.tf32.tf32.f32 "        \
        "{%0,%1,%2,%3},{%4,%5,%6,%7},{%8,%9},{%0,%1,%2,%3};"                  \
        : "+f"(d[0]), "+f"(d[1]), "+f"(d[2]), "+f"(d[3])                      \
        : "r"((a).x), "r"((a).y), "r"((a).z), "r"((a).w), "r"(b0), "r"(b1))

// terms 1+2 (Ah*Bh + Al*Bh) for all 8 n-tiles of one M-tile
#define MMA_T12(ACC, AH, AL)                                                  \
    MMA(ACC[0], AH, h0.x, h2.x); MMA(ACC[0], AL, h0.x, h2.x);                 \
    MMA(ACC[1], AH, h0.y, h2.y); MMA(ACC[1], AL, h0.y, h2.y);                 \
    MMA(ACC[2], AH, h0.z, h2.z); MMA(ACC[2], AL, h0.z, h2.z);                 \
    MMA(ACC[3], AH, h0.w, h2.w); MMA(ACC[3], AL, h0.w, h2.w);                 \
    MMA(ACC[4], AH, h1.x, h3.x); MMA(ACC[4], AL, h1.x, h3.x);                 \
    MMA(ACC[5], AH, h1.y, h3.y); MMA(ACC[5], AL, h1.y, h3.y);                 \
    MMA(ACC[6], AH, h1.z, h3.z); MMA(ACC[6], AL, h1.z, h3.z);                 \
    MMA(ACC[7], AH, h1.w, h3.w); MMA(ACC[7], AL, h1.w, h3.w)

// term 3 (Ah*Bl)
#define MMA_T3(ACC, AH)                                                       \
    MMA(ACC[0], AH, L0.x, L2.x);                                              \
    MMA(ACC[1], AH, L0.y, L2.y);                                              \
    MMA(ACC[2], AH, L0.z, L2.z);                                              \
    MMA(ACC[3], AH, L0.w, L2.w);                                              \
    MMA(ACC[4], AH, L1.x, L3.x);                                              \
    MMA(ACC[5], AH, L1.y, L3.y);                                              \
    MMA(ACC[6], AH, L1.z, L3.z);                                              \
    MMA(ACC[7], AH, L1.w, L3.w)

// ---------------------------------------------------------------------------
template<int TILES, int KS, int COUT, bool LN, bool PADK>
__device__ __forceinline__ void conv_pass(
    const uint4* __restrict__ Ah, const uint4* __restrict__ Al,
    const float* __restrict__ bias, const int* __restrict__ idxs)
{
    const int t = threadIdx.x;
    const int wid = t >> 5, lane = t & 31;
    const int gid = lane >> 2, tid4 = lane & 3;
    const int rot = (lane >> 1) & 3;
    const int oc0 = ((0 + rot) & 3) << 2;
    const int oc1 = ((1 + rot) & 3) << 2;
    const int oc2 = ((2 + rot) & 3) << 2;
    const int oc3 = ((3 + rot) & 3) << 2;

    float s1 = 0.f, s2 = 0.f;

    for (int tb = 0; tb < TILES; tb += 15) {
        const int T0 = tb + 2 * wid;
        const int Tb1 = T0 + 1;
        const bool act0 = (wid < 8) && (T0 < TILES);
        const bool act1 = act0 && (2 * wid + 1 < 15) && (Tb1 < TILES);

        if (act0) {
            float acc0[8][4], acc1[8][4];
            #pragma unroll
            for (int j = 0; j < 8; j++)
                #pragma unroll
                for (int p = 0; p < 4; p++) { acc0[j][p] = 0.f; acc1[j][p] = 0.f; }

            const uint4* A0h = Ah + (size_t)T0 * KS * 32 + lane;
            const uint4* A0l = Al + (size_t)T0 * KS * 32 + lane;
            const uint4* A1h = Ah + (size_t)Tb1 * KS * 32 + lane;
            const uint4* A1l = Al + (size_t)Tb1 * KS * 32 + lane;

            uint4 a0h = __ldg(A0h), a0l = __ldg(A0l);
            uint4 a1h = make_uint4(0,0,0,0), a1l = make_uint4(0,0,0,0);
            if (act1) { a1h = __ldg(A1h); a1l = __ldg(A1l); }

            #pragma unroll 1
            for (int s = 0; s < KS; s++) {
                const int sn = (s + 1 < KS) ? s + 1 : s;
                const uint4 n0h = __ldg(A0h + sn * 32);
                const uint4 n0l = __ldg(A0l + sn * 32);
                uint4 n1h = make_uint4(0,0,0,0), n1l = make_uint4(0,0,0,0);
                if (act1) { n1h = __ldg(A1h + sn * 32); n1l = __ldg(A1l + sn * 32); }

                const float* bh = &smem[XF_HI + s * 512 + lane * 16];
                const float* bl = &smem[XF_LO + s * 512 + lane * 16];

                {   // hi phase: terms Ah*Bh + Al*Bh
                    const uint4 h0 = *(const uint4*)(bh + oc0);
                    const uint4 h1 = *(const uint4*)(bh + oc1);
                    const uint4 h2 = *(const uint4*)(bh + oc2);
                    const uint4 h3 = *(const uint4*)(bh + oc3);
                    MMA_T12(acc0, a0h, a0l);
                    if (act1) { MMA_T12(acc1, a1h, a1l); }
                }
                {   // lo phase: term Ah*Bl
                    const uint4 L0 = *(const uint4*)(bl + oc0);
                    const uint4 L1 = *(const uint4*)(bl + oc1);
                    const uint4 L2 = *(const uint4*)(bl + oc2);
                    const uint4 L3 = *(const uint4*)(bl + oc3);
                    MMA_T3(acc0, a0h);
                    if (act1) { MMA_T3(acc1, a1h); }
                }

                a0h = n0h; a0l = n0l;
                if (act1) { a1h = n1h; a1l = n1l; }
            }

            // write D frags to Ych (local rows, padded stride)
            {
                const int lr0 = (T0 - tb) * 16 + gid;
                float* y0 = &smem[YCH + lr0 * YSTR + 2 * tid4];
                float* y1 = y0 + 8 * YSTR;
                #pragma unroll
                for (int j = 0; j < 8; j++) {
                    *(float2*)(y0 + 8 * j) = make_float2(acc0[j][0], acc0[j][1]);
                    *(float2*)(y1 + 8 * j) = make_float2(acc0[j][2], acc0[j][3]);
                }
            }
            if (act1) {
                const int lr1 = (Tb1 - tb) * 16 + gid;
                float* y0 = &smem[YCH + lr1 * YSTR + 2 * tid4];
                float* y1 = y0 + 8 * YSTR;
                #pragma unroll
                for (int j = 0; j < 8; j++) {
                    *(float2*)(y0 + 8 * j) = make_float2(acc1[j][0], acc1[j][1]);
                    *(float2*)(y1 + 8 * j) = make_float2(acc1[j][2], acc1[j][3]);
                }
            }
        }
        __syncthreads();

        // gather + bias for outputs covered by this chunk
        const int o0 = (tb * 16) / 3;
        const int no = (COUT - o0 < 80) ? (COUT - o0) : 80;
        for (int e = t; e < no * 64; e += NT) {
            const int ol = e >> 6;
            const int m  = e & 63;
            float v = 0.f;
            if (m != 0) {
                const int j3 = 3 * (m - 1);
                v = smem[YCH + (3 * ol    ) * YSTR + idxs[j3]]
                  + smem[YCH + (3 * ol + 1) * YSTR + idxs[j3 + 1]]
                  + smem[YCH + (3 * ol + 2) * YSTR + idxs[j3 + 2]]
                  + __ldg(bias + o0 + ol);
            }
            smem[XBUF + (o0 + ol) * 64 + m] = v;
            if (LN) { s1 += v; s2 += v * v; }
        }
        __syncthreads();
    }

    if (LN) {
        #pragma unroll
        for (int off = 16; off > 0; off >>= 1) {
            s1 += __shfl_down_sync(0xffffffffu, s1, off);
            s2 += __shfl_down_sync(0xffffffffu, s2, off);
        }
        if (lane == 0) { smem[S_RED + wid] = s1; smem[S_RED + 16 + wid] = s2; }
        __syncthreads();
        if (t == 0) {
            float S1 = 0.f, S2 = 0.f;
            #pragma unroll
            for (int w = 0; w < NW; w++) { S1 += smem[S_RED + w]; S2 += smem[S_RED + 16 + w]; }
            const float n = (float)(COUT * 64);
            const float mu = S1 / n;
            float var = (S2 - S1 * mu) / (n - 1.f);
            var = fmaxf(var, 0.f);
            smem[S_RED + 32] = mu;
            smem[S_RED + 33] = 1.f / (sqrtf(var) + 1e-5f);
        }
        __syncthreads();
        const float mu = smem[S_RED + 32], inv = smem[S_RED + 33];
        for (int e = t; e < COUT * 64; e += NT) {
            const float v = fmaxf((smem[XBUF + e] - mu) * inv, 0.f);
            split_store(v, xf_addr(e >> 6, e & 63));
        }
        if (PADK) {
            for (int e = t; e < 4 * 64; e += NT) {
                const int a = xf_addr(COUT + (e >> 6), e & 63);
                smem[XF_HI + a] = 0.f;
                smem[XF_LO + a] = 0.f;
            }
        }
        __syncthreads();
    }
}

// ---------------------------------------------------------------------------
// Prep: fragment-ready hi/lo A planes (m16n8k8 row-major A fragment order).
// ---------------------------------------------------------------------------
__device__ __forceinline__ float wget(const float* w, int COUT, int CIN, int r, int c) {
    if (r < 3 * COUT && c < CIN) {
        const int o = r / 3, k = r - o * 3;
        return w[(o * CIN + c) * 3 + k];
    }
    return 0.f;
}

__device__ __forceinline__ void prep_frag(const float* __restrict__ w,
    int COUT, int CIN, int KS, int f, uint4* __restrict__ Ah, uint4* __restrict__ Al)
{
    const int T = f / (KS * 32);
    const int rem = f - T * KS * 32;
    const int s = rem >> 5;
    const int l = rem & 31;
    const int gid = l >> 2, tid4 = l & 3;
    const int r0 = T * 16 + gid;
    const int c0 = s * 8 + tid4;

    const float v[4] = { wget(w, COUT, CIN, r0,     c0),
                         wget(w, COUT, CIN, r0 + 8, c0),
                         wget(w, COUT, CIN, r0,     c0 + 4),
                         wget(w, COUT, CIN, r0 + 8, c0 + 4) };
    uint32_t hi[4], lo[4];
    #pragma unroll
    for (int i = 0; i < 4; i++) {
        hi[i] = f2tf32(v[i]);
        lo[i] = f2tf32(v[i] - __uint_as_float(hi[i]));
    }
    Ah[f] = make_uint4(hi[0], hi[1], hi[2], hi[3]);
    Al[f] = make_uint4(lo[0], lo[1], lo[2], lo[3]);
}

__global__ void prep_weights(const float* __restrict__ c1w,
                             const float* __restrict__ c2w,
                             const float* __restrict__ c3w)
{
    const int f = blockIdx.x * 256 + threadIdx.x;
    if (f < N1)                prep_frag(c1w, 200, 200, KS1, f,            g_A1h, g_A1l);
    else if (f < N1 + N2)      prep_frag(c2w, 100, 200, KS2, f - N1,       g_A2h, g_A2l);
    else if (f < N1 + N2 + N3) prep_frag(c3w, 100, 100, KS3, f - N1 - N2,  g_A3h, g_A3l);
}

// ---------------------------------------------------------------------------
__global__ void __launch_bounds__(NT)
plan_cost_kernel(
    const float* __restrict__ trees, const int* __restrict__ indexes,
    const unsigned char* __restrict__ maskp,
    const float* __restrict__ c1b, const float* __restrict__ c2b,
    const float* __restrict__ c3b,
    const float* __restrict__ gw1, const float* __restrict__ gb1,
    const float* __restrict__ gw2, const float* __restrict__ gb2,
    const float* __restrict__ rw1, const float* __restrict__ rb1,
    const float* __restrict__ rw2, const float* __restrict__ rb2,
    const float* __restrict__ rw3, const float* __restrict__ rb3,
    float* __restrict__ out)
{
    const int b = blockIdx.x;
    const int t = threadIdx.x;
    int* idxs = (int*)&smem[S_IDX];

    {
        const int* isrc = indexes + (size_t)b * NIDX;
        for (int v = t; v < NIDX; v += NT) idxs[v] = isrc[v];
        const float* tb_ = trees + (size_t)b * 12800;
        for (int e = t; e < 12800; e += NT)
            split_store(tb_[e], xf_addr(e >> 6, e & 63));
    }
    __syncthreads();

    conv_pass<TIL1, KS1, 200, true,  false>(g_A1h, g_A1l, c1b, idxs);
    conv_pass<TIL2, KS2, 100, true,  true >(g_A2h, g_A2l, c2b, idxs);
    conv_pass<TIL3, KS3, 100, false, false>(g_A3h, g_A3l, c3b, idxs);

    const float* H3 = &smem[XBUF];     // emb[n,f] = H3[f*64 + n]
    float* gates  = &smem[S_GATES];
    float* alphas = &smem[S_ALPHA];
    float* comb   = &smem[S_COMB];
    float* z1s    = &smem[S_Z1];
    float* z2s    = &smem[S_Z2];
    const int wid = t >> 5, lid = t & 31;

    // gate head
    for (int n = wid; n < 64; n += NW) {
        float acc1 = 0.f, acc2 = 0.f;
        const int h1 = lid;
        const int h2 = lid + 32;
        const float* w1p = gw1 + h1 * 100;
        const float* w2p = gw1 + h2 * 100;
        for (int f = 0; f < 100; f++) {
            const float e = H3[f * 64 + n];
            acc1 += e * __ldg(w1p + f);
            if (h2 < 50) acc2 += e * __ldg(w2p + f);
        }
        float contrib = fmaxf(acc1 + __ldg(gb1 + h1), 0.f) * __ldg(gw2 + h1);
        if (h2 < 50)
            contrib += fmaxf(acc2 + __ldg(gb1 + h2), 0.f) * __ldg(gw2 + h2);
        #pragma unroll
        for (int off = 16; off > 0; off >>= 1)
            contrib += __shfl_down_sync(0xffffffffu, contrib, off);
        if (lid == 0) {
            float gv = contrib + __ldg(gb2);
            if (maskp[(size_t)b * 64 + n]) gv = -INFINITY;
            gates[n] = gv;
        }
    }
    __syncthreads();

    // softmax over 64 nodes (warp 0)
    if (wid == 0) {
        const float v1 = gates[lid], v2 = gates[lid + 32];
        float m = fmaxf(v1, v2);
        #pragma unroll
        for (int off = 16; off > 0; off >>= 1)
            m = fmaxf(m, __shfl_xor_sync(0xffffffffu, m, off));
        const float e1 = expf(v1 - m), e2 = expf(v2 - m);
        float s = e1 + e2;
        #pragma unroll
        for (int off = 16; off > 0; off >>= 1)
            s += __shfl_xor_sync(0xffffffffu, s, off);
        const float invs = 1.f / s;
        alphas[lid] = e1 * invs;
        alphas[lid + 32] = e2 * invs;
    }
    __syncthreads();

    // pooled + root -> combined
    if (t < 100) {
        const float* row = H3 + t * 64;
        float acc = 0.f;
        #pragma unroll 4
        for (int n = 0; n < 64; n++) acc += alphas[n] * row[n];
        const float rootv = row[1];
        comb[t] = rootv;
        comb[100 + t] = acc;
        out[BATCH + (size_t)b * 200 + t] = rootv;
        out[BATCH + (size_t)b * 200 + 100 + t] = acc;
    }
    __syncthreads();

    // regressor MLP
    if (t < 128) {
        float acc = __ldg(rb1 + t);
        const float* wr = rw1 + t * 200;
        #pragma unroll 4
        for (int c = 0; c < 200; c++) acc += comb[c] * __ldg(wr + c);
        z1s[t] = fmaxf(acc, 0.f);
    }
    __syncthreads();
    if (t < 64) {
        float acc = __ldg(rb2 + t);
        const float* wr = rw2 + t * 128;
        #pragma unroll 4
        for (int c = 0; c < 128; c++) acc += z1s[c] * __ldg(wr + c);
        z2s[t] = fmaxf(acc, 0.f);
    }
    __syncthreads();
    if (wid == 0) {
        float acc = z2s[lid] * __ldg(rw3 + lid)
                  + z2s[lid + 32] * __ldg(rw3 + lid + 32);
        #pragma unroll
        for (int off = 16; off > 0; off >>= 1)
            acc += __shfl_down_sync(0xffffffffu, acc, off);
        if (lid == 0) out[b] = acc + __ldg(rb3);
    }
}

// ---------------------------------------------------------------------------
extern "C" void kernel_launch(void* const* d_in, const int* in_sizes, int n_in,
                              void* d_out, int out_size)
{
    (void)in_sizes; (void)n_in; (void)out_size;
    const size_t smem_bytes = (size_t)SMEM_FLOATS * sizeof(float);
    cudaFuncSetAttribute(plan_cost_kernel,
                         cudaFuncAttributeMaxDynamicSharedMemorySize,
                         (int)smem_bytes);

    prep_weights<<<(N1 + N2 + N3 + 255) / 256, 256>>>(
        (const float*)d_in[3], (const float*)d_in[5], (const float*)d_in[7]);

    plan_cost_kernel<<<BATCH, NT, smem_bytes>>>(
        (const float*)d_in[0],
        (const int*)d_in[1],
        (const unsigned char*)d_in[2],
        (const float*)d_in[4],
        (const float*)d_in[6],
        (const float*)d_in[8],
        (const float*)d_in[9],  (const float*)d_in[10],
        (const float*)d_in[11], (const float*)d_in[12],
        (const float*)d_in[13], (const float*)d_in[14],
        (const float*)d_in[15], (const float*)d_in[16],
        (const float*)d_in[17], (const float*)d_in[18],
        (float*)d_out);
}

// round 11
// speedup vs baseline: 1.7172x; 1.0682x over previous
#include <cuda_runtime.h>
#include <cstdint>
#include <math.h>

// ============================================================================
// PlanCostEstimatorFull — round 11 (identical to round 10; round-10 bench was
// an infra failure, re-benching the same kernel)
// tf32x3 mma.sync conv stack, per-batch CTA.
// 512 threads / 16 warps; 15 MMA warps x 1 M-tile each (vs 8x2) for
// latency hiding (3.75 TC-feeding warps/SMSP); lower reg pressure.
// ============================================================================

#define BATCH 2048
#define NT    512
#define NW    16
#define NIDX  189

#define TIL1  38
#define KS1   25
#define TIL2  19
#define KS2   25
#define TIL3  19
#define KS3   13

#define N1 (TIL1*KS1*32)   // 30400
#define N2 (TIL2*KS2*32)   // 15200
#define N3 (TIL3*KS3*32)   // 7904

__device__ uint4 g_A1h[N1], g_A1l[N1];
__device__ uint4 g_A2h[N2], g_A2l[N2];
__device__ uint4 g_A3h[N3], g_A3l[N3];

// smem offsets (floats)
#define XF_HI   0
#define XF_LO   12800
#define XBUF    25600
#define YCH     38400
#define YSTR    68
#define S_IDX   54720   /* 192 ints */
#define S_RED   54912   /* 40 */
#define S_GATES 54952
#define S_ALPHA 55016
#define S_COMB  55080
#define S_Z1    55280
#define S_Z2    55408
#define SMEM_FLOATS 55480

extern __shared__ float smem[];

__device__ __forceinline__ uint32_t f2tf32(float f) {
    uint32_t u;
    asm("cvt.rna.tf32.f32 %0, %1;" : "=r"(u) : "f"(f));
    return u;
}

// fragment-major activation address with chunk swizzle (conflict-free reads):
// block (=lane within k-step) b, 16-float payload split in 4 chunks; logical
// chunk c stored at physical slot (c + (b>>1)) & 3.
__device__ __forceinline__ int xf_addr(int i, int m) {
    const int blk = (i >> 3) * 32 + ((m & 7) * 4 | (i & 3));
    const int off = (((i >> 2) & 1) << 3) + (m >> 3);       // 0..15
    const int c   = off >> 2;
    const int w   = off & 3;
    const int rot = (blk >> 1) & 3;                          // == (lane>>1)&3
    return blk * 16 + (((c + rot) & 3) << 2) + w;
}

__device__ __forceinline__ void split_store(float v, int addr) {
    const uint32_t h = f2tf32(v);
    const float hf = __uint_as_float(h);
    const uint32_t l = f2tf32(v - hf);
    smem[XF_HI + addr] = hf;
    smem[XF_LO + addr] = __uint_as_float(l);
}

#define MMA(d, a, b0, b1)                                                     \
    asm volatile("mma.sync.aligned.m16n8k8.row.col.f32.tf32.tf32.f32 "        \
        "{%0,%1,%2,%3},{%4,%5,%6,%7},{%8,%9},{%0,%1,%2,%3};"                  \
        : "+f"(d[0]), "+f"(d[1]), "+f"(d[2]), "+f"(d[3])                      \
        : "r"((a).x), "r"((a).y), "r"((a).z), "r"((a).w), "r"(b0), "r"(b1))

// terms 1+2 (Ah*Bh + Al*Bh) for all 8 n-tiles of one M-tile
#define MMA_T12(ACC, AH, AL)                                                  \
    MMA(ACC[0], AH, h0.x, h2.x); MMA(ACC[0], AL, h0.x, h2.x);                 \
    MMA(ACC[1], AH, h0.y, h2.y); MMA(ACC[1], AL, h0.y, h2.y);                 \
    MMA(ACC[2], AH, h0.z, h2.z); MMA(ACC[2], AL, h0.z, h2.z);                 \
    MMA(ACC[3], AH, h0.w, h2.w); MMA(ACC[3], AL, h0.w, h2.w);                 \
    MMA(ACC[4], AH, h1.x, h3.x); MMA(ACC[4], AL, h1.x, h3.x);                 \
    MMA(ACC[5], AH, h1.y, h3.y); MMA(ACC[5], AL, h1.y, h3.y);                 \
    MMA(ACC[6], AH, h1.z, h3.z); MMA(ACC[6], AL, h1.z, h3.z);                 \
    MMA(ACC[7], AH, h1.w, h3.w); MMA(ACC[7], AL, h1.w, h3.w)

// term 3 (Ah*Bl)
#define MMA_T3(ACC, AH)                                                       \
    MMA(ACC[0], AH, L0.x, L2.x);                                              \
    MMA(ACC[1], AH, L0.y, L2.y);                                              \
    MMA(ACC[2], AH, L0.z, L2.z);                                              \
    MMA(ACC[3], AH, L0.w, L2.w);                                              \
    MMA(ACC[4], AH, L1.x, L3.x);                                              \
    MMA(ACC[5], AH, L1.y, L3.y);                                              \
    MMA(ACC[6], AH, L1.z, L3.z);                                              \
    MMA(ACC[7], AH, L1.w, L3.w)

// ---------------------------------------------------------------------------
template<int TILES, int KS, int COUT, bool LN, bool PADK>
__device__ __forceinline__ void conv_pass(
    const uint4* __restrict__ Ah, const uint4* __restrict__ Al,
    const float* __restrict__ bias, const int* __restrict__ idxs)
{
    const int t = threadIdx.x;
    const int wid = t >> 5, lane = t & 31;
    const int gid = lane >> 2, tid4 = lane & 3;
    const int rot = (lane >> 1) & 3;
    const int oc0 = ((0 + rot) & 3) << 2;
    const int oc1 = ((1 + rot) & 3) << 2;
    const int oc2 = ((2 + rot) & 3) << 2;
    const int oc3 = ((3 + rot) & 3) << 2;

    float s1 = 0.f, s2 = 0.f;

    for (int tb = 0; tb < TILES; tb += 15) {
        const int T = tb + wid;
        const bool act = (wid < 15) && (T < TILES);

        if (act) {
            float acc[8][4];
            #pragma unroll
            for (int j = 0; j < 8; j++)
                #pragma unroll
                for (int p = 0; p < 4; p++) acc[j][p] = 0.f;

            const uint4* A0h = Ah + (size_t)T * KS * 32 + lane;
            const uint4* A0l = Al + (size_t)T * KS * 32 + lane;

            uint4 ah = __ldg(A0h);
            uint4 al = __ldg(A0l);

            #pragma unroll 1
            for (int s = 0; s < KS; s++) {
                const int sn = (s + 1 < KS) ? s + 1 : s;
                const uint4 nh = __ldg(A0h + sn * 32);
                const uint4 nl = __ldg(A0l + sn * 32);

                const float* bh = &smem[XF_HI + s * 512 + lane * 16];
                const float* bl = &smem[XF_LO + s * 512 + lane * 16];

                {   // hi phase: terms Ah*Bh + Al*Bh
                    const uint4 h0 = *(const uint4*)(bh + oc0);
                    const uint4 h1 = *(const uint4*)(bh + oc1);
                    const uint4 h2 = *(const uint4*)(bh + oc2);
                    const uint4 h3 = *(const uint4*)(bh + oc3);
                    MMA_T12(acc, ah, al);
                }
                {   // lo phase: term Ah*Bl
                    const uint4 L0 = *(const uint4*)(bl + oc0);
                    const uint4 L1 = *(const uint4*)(bl + oc1);
                    const uint4 L2 = *(const uint4*)(bl + oc2);
                    const uint4 L3 = *(const uint4*)(bl + oc3);
                    MMA_T3(acc, ah);
                }

                ah = nh; al = nl;
            }

            // write D frags to Ych (local rows, padded stride)
            const int lr = (T - tb) * 16 + gid;
            float* y0 = &smem[YCH + lr * YSTR + 2 * tid4];
            float* y1 = y0 + 8 * YSTR;
            #pragma unroll
            for (int j = 0; j < 8; j++) {
                *(float2*)(y0 + 8 * j) = make_float2(acc[j][0], acc[j][1]);
                *(float2*)(y1 + 8 * j) = make_float2(acc[j][2], acc[j][3]);
            }
        }
        __syncthreads();

        // gather + bias for outputs covered by this chunk
        const int o0 = (tb * 16) / 3;
        const int no = (COUT - o0 < 80) ? (COUT - o0) : 80;
        for (int e = t; e < no * 64; e += NT) {
            const int ol = e >> 6;
            const int m  = e & 63;
            float v = 0.f;
            if (m != 0) {
                const int j3 = 3 * (m - 1);
                v = smem[YCH + (3 * ol    ) * YSTR + idxs[j3]]
                  + smem[YCH + (3 * ol + 1) * YSTR + idxs[j3 + 1]]
                  + smem[YCH + (3 * ol + 2) * YSTR + idxs[j3 + 2]]
                  + __ldg(bias + o0 + ol);
            }
            smem[XBUF + (o0 + ol) * 64 + m] = v;
            if (LN) { s1 += v; s2 += v * v; }
        }
        __syncthreads();
    }

    if (LN) {
        #pragma unroll
        for (int off = 16; off > 0; off >>= 1) {
            s1 += __shfl_down_sync(0xffffffffu, s1, off);
            s2 += __shfl_down_sync(0xffffffffu, s2, off);
        }
        if (lane == 0) { smem[S_RED + wid] = s1; smem[S_RED + 16 + wid] = s2; }
        __syncthreads();
        if (t == 0) {
            float S1 = 0.f, S2 = 0.f;
            #pragma unroll
            for (int w = 0; w < NW; w++) { S1 += smem[S_RED + w]; S2 += smem[S_RED + 16 + w]; }
            const float n = (float)(COUT * 64);
            const float mu = S1 / n;
            float var = (S2 - S1 * mu) / (n - 1.f);
            var = fmaxf(var, 0.f);
            smem[S_RED + 32] = mu;
            smem[S_RED + 33] = 1.f / (sqrtf(var) + 1e-5f);
        }
        __syncthreads();
        const float mu = smem[S_RED + 32], inv = smem[S_RED + 33];
        for (int e = t; e < COUT * 64; e += NT) {
            const float v = fmaxf((smem[XBUF + e] - mu) * inv, 0.f);
            split_store(v, xf_addr(e >> 6, e & 63));
        }
        if (PADK) {
            for (int e = t; e < 4 * 64; e += NT) {
                const int a = xf_addr(COUT + (e >> 6), e & 63);
                smem[XF_HI + a] = 0.f;
                smem[XF_LO + a] = 0.f;
            }
        }
        __syncthreads();
    }
}

// ---------------------------------------------------------------------------
// Prep: fragment-ready hi/lo A planes (m16n8k8 row-major A fragment order).
// ---------------------------------------------------------------------------
__device__ __forceinline__ float wget(const float* w, int COUT, int CIN, int r, int c) {
    if (r < 3 * COUT && c < CIN) {
        const int o = r / 3, k = r - o * 3;
        return w[(o * CIN + c) * 3 + k];
    }
    return 0.f;
}

__device__ __forceinline__ void prep_frag(const float* __restrict__ w,
    int COUT, int CIN, int KS, int f, uint4* __restrict__ Ah, uint4* __restrict__ Al)
{
    const int T = f / (KS * 32);
    const int rem = f - T * KS * 32;
    const int s = rem >> 5;
    const int l = rem & 31;
    const int gid = l >> 2, tid4 = l & 3;
    const int r0 = T * 16 + gid;
    const int c0 = s * 8 + tid4;

    const float v[4] = { wget(w, COUT, CIN, r0,     c0),
                         wget(w, COUT, CIN, r0 + 8, c0),
                         wget(w, COUT, CIN, r0,     c0 + 4),
                         wget(w, COUT, CIN, r0 + 8, c0 + 4) };
    uint32_t hi[4], lo[4];
    #pragma unroll
    for (int i = 0; i < 4; i++) {
        hi[i] = f2tf32(v[i]);
        lo[i] = f2tf32(v[i] - __uint_as_float(hi[i]));
    }
    Ah[f] = make_uint4(hi[0], hi[1], hi[2], hi[3]);
    Al[f] = make_uint4(lo[0], lo[1], lo[2], lo[3]);
}

__global__ void prep_weights(const float* __restrict__ c1w,
                             const float* __restrict__ c2w,
                             const float* __restrict__ c3w)
{
    const int f = blockIdx.x * 256 + threadIdx.x;
    if (f < N1)                prep_frag(c1w, 200, 200, KS1, f,            g_A1h, g_A1l);
    else if (f < N1 + N2)      prep_frag(c2w, 100, 200, KS2, f - N1,       g_A2h, g_A2l);
    else if (f < N1 + N2 + N3) prep_frag(c3w, 100, 100, KS3, f - N1 - N2,  g_A3h, g_A3l);
}

// ---------------------------------------------------------------------------
__global__ void __launch_bounds__(NT)
plan_cost_kernel(
    const float* __restrict__ trees, const int* __restrict__ indexes,
    const unsigned char* __restrict__ maskp,
    const float* __restrict__ c1b, const float* __restrict__ c2b,
    const float* __restrict__ c3b,
    const float* __restrict__ gw1, const float* __restrict__ gb1,
    const float* __restrict__ gw2, const float* __restrict__ gb2,
    const float* __restrict__ rw1, const float* __restrict__ rb1,
    const float* __restrict__ rw2, const float* __restrict__ rb2,
    const float* __restrict__ rw3, const float* __restrict__ rb3,
    float* __restrict__ out)
{
    const int b = blockIdx.x;
    const int t = threadIdx.x;
    int* idxs = (int*)&smem[S_IDX];

    {
        const int* isrc = indexes + (size_t)b * NIDX;
        for (int v = t; v < NIDX; v += NT) idxs[v] = isrc[v];
        const float* tb_ = trees + (size_t)b * 12800;
        for (int e = t; e < 12800; e += NT)
            split_store(tb_[e], xf_addr(e >> 6, e & 63));
    }
    __syncthreads();

    conv_pass<TIL1, KS1, 200, true,  false>(g_A1h, g_A1l, c1b, idxs);
    conv_pass<TIL2, KS2, 100, true,  true >(g_A2h, g_A2l, c2b, idxs);
    conv_pass<TIL3, KS3, 100, false, false>(g_A3h, g_A3l, c3b, idxs);

    const float* H3 = &smem[XBUF];     // emb[n,f] = H3[f*64 + n]
    float* gates  = &smem[S_GATES];
    float* alphas = &smem[S_ALPHA];
    float* comb   = &smem[S_COMB];
    float* z1s    = &smem[S_Z1];
    float* z2s    = &smem[S_Z2];
    const int wid = t >> 5, lid = t & 31;

    // gate head
    for (int n = wid; n < 64; n += NW) {
        float acc1 = 0.f, acc2 = 0.f;
        const int h1 = lid;
        const int h2 = lid + 32;
        const float* w1p = gw1 + h1 * 100;
        const float* w2p = gw1 + h2 * 100;
        for (int f = 0; f < 100; f++) {
            const float e = H3[f * 64 + n];
            acc1 += e * __ldg(w1p + f);
            if (h2 < 50) acc2 += e * __ldg(w2p + f);
        }
        float contrib = fmaxf(acc1 + __ldg(gb1 + h1), 0.f) * __ldg(gw2 + h1);
        if (h2 < 50)
            contrib += fmaxf(acc2 + __ldg(gb1 + h2), 0.f) * __ldg(gw2 + h2);
        #pragma unroll
        for (int off = 16; off > 0; off >>= 1)
            contrib += __shfl_down_sync(0xffffffffu, contrib, off);
        if (lid == 0) {
            float gv = contrib + __ldg(gb2);
            if (maskp[(size_t)b * 64 + n]) gv = -INFINITY;
            gates[n] = gv;
        }
    }
    __syncthreads();

    // softmax over 64 nodes (warp 0)
    if (wid == 0) {
        const float v1 = gates[lid], v2 = gates[lid + 32];
        float m = fmaxf(v1, v2);
        #pragma unroll
        for (int off = 16; off > 0; off >>= 1)
            m = fmaxf(m, __shfl_xor_sync(0xffffffffu, m, off));
        const float e1 = expf(v1 - m), e2 = expf(v2 - m);
        float s = e1 + e2;
        #pragma unroll
        for (int off = 16; off > 0; off >>= 1)
            s += __shfl_xor_sync(0xffffffffu, s, off);
        const float invs = 1.f / s;
        alphas[lid] = e1 * invs;
        alphas[lid + 32] = e2 * invs;
    }
    __syncthreads();

    // pooled + root -> combined
    if (t < 100) {
        const float* row = H3 + t * 64;
        float acc = 0.f;
        #pragma unroll 4
        for (int n = 0; n < 64; n++) acc += alphas[n] * row[n];
        const float rootv = row[1];
        comb[t] = rootv;
        comb[100 + t] = acc;
        out[BATCH + (size_t)b * 200 + t] = rootv;
        out[BATCH + (size_t)b * 200 + 100 + t] = acc;
    }
    __syncthreads();

    // regressor MLP
    if (t < 128) {
        float acc = __ldg(rb1 + t);
        const float* wr = rw1 + t * 200;
        #pragma unroll 4
        for (int c = 0; c < 200; c++) acc += comb[c] * __ldg(wr + c);
        z1s[t] = fmaxf(acc, 0.f);
    }
    __syncthreads();
    if (t < 64) {
        float acc = __ldg(rb2 + t);
        const float* wr = rw2 + t * 128;
        #pragma unroll 4
        for (int c = 0; c < 128; c++) acc += z1s[c] * __ldg(wr + c);
        z2s[t] = fmaxf(acc, 0.f);
    }
    __syncthreads();
    if (wid == 0) {
        float acc = z2s[lid] * __ldg(rw3 + lid)
                  + z2s[lid + 32] * __ldg(rw3 + lid + 32);
        #pragma unroll
        for (int off = 16; off > 0; off >>= 1)
            acc += __shfl_down_sync(0xffffffffu, acc, off);
        if (lid == 0) out[b] = acc + __ldg(rb3);
    }
}

// ---------------------------------------------------------------------------
extern "C" void kernel_launch(void* const* d_in, const int* in_sizes, int n_in,
                              void* d_out, int out_size)
{
    (void)in_sizes; (void)n_in; (void)out_size;
    const size_t smem_bytes = (size_t)SMEM_FLOATS * sizeof(float);
    cudaFuncSetAttribute(plan_cost_kernel,
                         cudaFuncAttributeMaxDynamicSharedMemorySize,
                         (int)smem_bytes);

    prep_weights<<<(N1 + N2 + N3 + 255) / 256, 256>>>(
        (const float*)d_in[3], (const float*)d_in[5], (const float*)d_in[7]);

    plan_cost_kernel<<<BATCH, NT, smem_bytes>>>(
        (const float*)d_in[0],
        (const int*)d_in[1],
        (const unsigned char*)d_in[2],
        (const float*)d_in[4],
        (const float*)d_in[6],
        (const float*)d_in[8],
        (const float*)d_in[9],  (const float*)d_in[10],
        (const float*)d_in[11], (const float*)d_in[12],
        (const float*)d_in[13], (const float*)d_in[14],
        (const float*)d_in[15], (const float*)d_in[16],
        (const float*)d_in[17], (const float*)d_in[18],
        (float*)d_out);
}

// round 12
// speedup vs baseline: 2.1203x; 1.2348x over previous
#include <cuda_runtime.h>
#include <cuda_bf16.h>
#include <cstdint>
#include <math.h>

// ============================================================================
// PlanCostEstimatorFull — round 12
// bf16x3 mma.sync m16n8k16 conv stack (was tf32x3 m16n8k8): halves MMA count,
// B LDS bytes, A LDG bytes, and k-steps. 2-deep A prefetch. Same conflict-free
// swizzled B layout (64B/lane blocks), same chunked gather/LN epilogues.
// ============================================================================

#define BATCH 2048
#define NT    512
#define NW    16
#define NIDX  189

#define TIL1  38
#define KS1   13
#define TIL2  19
#define KS2   13
#define TIL3  19
#define KS3   7

#define N1 (TIL1*KS1*32)   // 15808
#define N2 (TIL2*KS2*32)   // 7904
#define N3 (TIL3*KS3*32)   // 4256

__device__ uint4 g_A1h[N1], g_A1l[N1];
__device__ uint4 g_A2h[N2], g_A2l[N2];
__device__ uint4 g_A3h[N3], g_A3l[N3];

// smem word (4B) offsets
#define XF_HI   0        /* 13*512 = 6656 words of bf16x2 */
#define XF_LO   6656
#define XBUF    13312    /* 12800 fp32 */
#define YCH     26112    /* 240 rows x 68 stride */
#define YSTR    68
#define S_IDX   42432    /* 192 ints */
#define S_RED   42624    /* 40 */
#define S_GATES 42664
#define S_ALPHA 42728
#define S_COMB  42792
#define S_Z1    42992
#define S_Z2    43120
#define SMEM_FLOATS 43184

extern __shared__ float smem[];

// ---------------------------------------------------------------------------
// B-plane addressing (bf16 element index within a plane).
// m16n8k16 B frag: lane l (= g*4+t, g=n-within-tile, t=row-pair idx) holds
// regs r = j*2+eps (j = n-tile, eps = +8 k-half); each reg = bf16 pair
// (k=2t+0, 2t+1) [+8 if eps]. 16 regs = 64B block per lane per k-step; the
// four 16B chunks are rotated by (l>>1)&3 for conflict-free LDS.128.
// ---------------------------------------------------------------------------
__device__ __forceinline__ int bf_addr(int i, int m) {
    const int s  = i >> 4, kk = i & 15;
    const int t  = (kk >> 1) & 3, d = kk & 1, e = kk >> 3;
    const int g  = m & 7, j = m >> 3;
    const int l  = g * 4 + t;
    const int r  = j * 2 + e, c = r >> 2, w = r & 3;
    const int ph = (c + ((l >> 1) & 3)) & 3;
    return (s * 512 + l * 16 + ph * 4 + w) * 2 + d;
}

__device__ __forceinline__ void split_store(float v, int a) {
    const __nv_bfloat16 h = __float2bfloat16(v);
    const __nv_bfloat16 lo = __float2bfloat16(v - __bfloat162float(h));
    __nv_bfloat16* p = (__nv_bfloat16*)smem;
    p[a] = h;                 // XF_HI plane (word 0 base)
    p[13312 + a] = lo;        // XF_LO plane (word 6656 base)
}

__device__ __forceinline__ void zero_store(int a) {
    __nv_bfloat16* p = (__nv_bfloat16*)smem;
    const __nv_bfloat16 z = __float2bfloat16(0.f);
    p[a] = z;
    p[13312 + a] = z;
}

#define MMAB(d, a, b0, b1)                                                    \
    asm volatile("mma.sync.aligned.m16n8k16.row.col.f32.bf16.bf16.f32 "       \
        "{%0,%1,%2,%3},{%4,%5,%6,%7},{%8,%9},{%0,%1,%2,%3};"                  \
        : "+f"(d[0]), "+f"(d[1]), "+f"(d[2]), "+f"(d[3])                      \
        : "r"((a).x), "r"((a).y), "r"((a).z), "r"((a).w), "r"(b0), "r"(b1))

// terms 1+2 (Ah*Bh + Al*Bh), 8 n-tiles; chunk c holds n-tiles 2c, 2c+1
#define MMA_T12(ACC, AH, AL)                                                  \
    MMAB(ACC[0], AH, h0.x, h0.y); MMAB(ACC[0], AL, h0.x, h0.y);               \
    MMAB(ACC[1], AH, h0.z, h0.w); MMAB(ACC[1], AL, h0.z, h0.w);               \
    MMAB(ACC[2], AH, h1.x, h1.y); MMAB(ACC[2], AL, h1.x, h1.y);               \
    MMAB(ACC[3], AH, h1.z, h1.w); MMAB(ACC[3], AL, h1.z, h1.w);               \
    MMAB(ACC[4], AH, h2.x, h2.y); MMAB(ACC[4], AL, h2.x, h2.y);               \
    MMAB(ACC[5], AH, h2.z, h2.w); MMAB(ACC[5], AL, h2.z, h2.w);               \
    MMAB(ACC[6], AH, h3.x, h3.y); MMAB(ACC[6], AL, h3.x, h3.y);               \
    MMAB(ACC[7], AH, h3.z, h3.w); MMAB(ACC[7], AL, h3.z, h3.w)

// term 3 (Ah*Bl)
#define MMA_T3(ACC, AH)                                                       \
    MMAB(ACC[0], AH, L0.x, L0.y); MMAB(ACC[1], AH, L0.z, L0.w);               \
    MMAB(ACC[2], AH, L1.x, L1.y); MMAB(ACC[3], AH, L1.z, L1.w);               \
    MMAB(ACC[4], AH, L2.x, L2.y); MMAB(ACC[5], AH, L2.z, L2.w);               \
    MMAB(ACC[6], AH, L3.x, L3.y); MMAB(ACC[7], AH, L3.z, L3.w)

// ---------------------------------------------------------------------------
template<int TILES, int KS, int COUT, bool LN, int PADN>
__device__ __forceinline__ void conv_pass(
    const uint4* __restrict__ Ah, const uint4* __restrict__ Al,
    const float* __restrict__ bias, const int* __restrict__ idxs)
{
    const int t = threadIdx.x;
    const int wid = t >> 5, lane = t & 31;
    const int gid = lane >> 2, tid4 = lane & 3;
    const int rot = (lane >> 1) & 3;
    const int oc0 = ((0 + rot) & 3) << 2;
    const int oc1 = ((1 + rot) & 3) << 2;
    const int oc2 = ((2 + rot) & 3) << 2;
    const int oc3 = ((3 + rot) & 3) << 2;

    float s1 = 0.f, s2 = 0.f;

    for (int tb = 0; tb < TILES; tb += 15) {
        const int T = tb + wid;
        const bool act = (wid < 15) && (T < TILES);

        if (act) {
            float acc[8][4];
            #pragma unroll
            for (int j = 0; j < 8; j++)
                #pragma unroll
                for (int p = 0; p < 4; p++) acc[j][p] = 0.f;

            const uint4* A0h = Ah + (size_t)T * KS * 32 + lane;
            const uint4* A0l = Al + (size_t)T * KS * 32 + lane;

            // 2-deep A prefetch (KS >= 2 always)
            uint4 c0h = __ldg(A0h),      c0l = __ldg(A0l);
            uint4 c1h = __ldg(A0h + 32), c1l = __ldg(A0l + 32);

            #pragma unroll 1
            for (int s = 0; s < KS; s++) {
                const int sn = (s + 2 < KS) ? s + 2 : KS - 1;
                const uint4 nh = __ldg(A0h + sn * 32);
                const uint4 nl = __ldg(A0l + sn * 32);

                const float* bh = &smem[XF_HI + s * 512 + lane * 16];
                const float* bl = &smem[XF_LO + s * 512 + lane * 16];

                {   // hi phase: Ah*Bh + Al*Bh
                    const uint4 h0 = *(const uint4*)(bh + oc0);
                    const uint4 h1 = *(const uint4*)(bh + oc1);
                    const uint4 h2 = *(const uint4*)(bh + oc2);
                    const uint4 h3 = *(const uint4*)(bh + oc3);
                    MMA_T12(acc, c0h, c0l);
                }
                {   // lo phase: Ah*Bl
                    const uint4 L0 = *(const uint4*)(bl + oc0);
                    const uint4 L1 = *(const uint4*)(bl + oc1);
                    const uint4 L2 = *(const uint4*)(bl + oc2);
                    const uint4 L3 = *(const uint4*)(bl + oc3);
                    MMA_T3(acc, c0h);
                }

                c0h = c1h; c0l = c1l;
                c1h = nh;  c1l = nl;
            }

            // write D frags to Ych (m16n8k16 D layout == m16n8k8)
            const int lr = (T - tb) * 16 + gid;
            float* y0 = &smem[YCH + lr * YSTR + 2 * tid4];
            float* y1 = y0 + 8 * YSTR;
            #pragma unroll
            for (int j = 0; j < 8; j++) {
                *(float2*)(y0 + 8 * j) = make_float2(acc[j][0], acc[j][1]);
                *(float2*)(y1 + 8 * j) = make_float2(acc[j][2], acc[j][3]);
            }
        }
        __syncthreads();

        // gather + bias for outputs covered by this chunk
        const int o0 = (tb * 16) / 3;
        const int no = (COUT - o0 < 80) ? (COUT - o0) : 80;
        for (int e = t; e < no * 64; e += NT) {
            const int ol = e >> 6;
            const int m  = e & 63;
            float v = 0.f;
            if (m != 0) {
                const int j3 = 3 * (m - 1);
                v = smem[YCH + (3 * ol    ) * YSTR + idxs[j3]]
                  + smem[YCH + (3 * ol + 1) * YSTR + idxs[j3 + 1]]
                  + smem[YCH + (3 * ol + 2) * YSTR + idxs[j3 + 2]]
                  + __ldg(bias + o0 + ol);
            }
            smem[XBUF + (o0 + ol) * 64 + m] = v;
            if (LN) { s1 += v; s2 += v * v; }
        }
        __syncthreads();
    }

    if (LN) {
        #pragma unroll
        for (int off = 16; off > 0; off >>= 1) {
            s1 += __shfl_down_sync(0xffffffffu, s1, off);
            s2 += __shfl_down_sync(0xffffffffu, s2, off);
        }
        if (lane == 0) { smem[S_RED + wid] = s1; smem[S_RED + 16 + wid] = s2; }
        __syncthreads();
        if (t == 0) {
            float S1 = 0.f, S2 = 0.f;
            #pragma unroll
            for (int w = 0; w < NW; w++) { S1 += smem[S_RED + w]; S2 += smem[S_RED + 16 + w]; }
            const float n = (float)(COUT * 64);
            const float mu = S1 / n;
            float var = (S2 - S1 * mu) / (n - 1.f);
            var = fmaxf(var, 0.f);
            smem[S_RED + 32] = mu;
            smem[S_RED + 33] = 1.f / (sqrtf(var) + 1e-5f);
        }
        __syncthreads();
        const float mu = smem[S_RED + 32], inv = smem[S_RED + 33];
        for (int e = t; e < COUT * 64; e += NT) {
            const float v = fmaxf((smem[XBUF + e] - mu) * inv, 0.f);
            split_store(v, bf_addr(e >> 6, e & 63));
        }
        if (PADN > 0) {
            for (int e = t; e < PADN * 64; e += NT)
                zero_store(bf_addr(COUT + (e >> 6), e & 63));
        }
        __syncthreads();
    }
}

// ---------------------------------------------------------------------------
// Prep: bf16 hi/lo A fragments (m16n8k16 row-major A layout).
// a0 = {A[g][2t],A[g][2t+1]}, a1 = rows+8, a2 = cols+8, a3 = both.
// ---------------------------------------------------------------------------
__device__ __forceinline__ float wget(const float* w, int COUT, int CIN, int r, int c) {
    if (r < 3 * COUT && c < CIN) {
        const int o = r / 3, k = r - o * 3;
        return w[(o * CIN + c) * 3 + k];
    }
    return 0.f;
}

__device__ __forceinline__ void prep_frag(const float* __restrict__ w,
    int COUT, int CIN, int KS, int f, uint4* __restrict__ Ah, uint4* __restrict__ Al)
{
    const int T = f / (KS * 32);
    const int rem = f - T * KS * 32;
    const int s = rem >> 5;
    const int l = rem & 31;
    const int g = l >> 2, t = l & 3;
    const int r0 = T * 16 + g;
    const int c0 = s * 16 + 2 * t;

    const float v[8] = {
        wget(w, COUT, CIN, r0,     c0),     wget(w, COUT, CIN, r0,     c0 + 1),
        wget(w, COUT, CIN, r0 + 8, c0),     wget(w, COUT, CIN, r0 + 8, c0 + 1),
        wget(w, COUT, CIN, r0,     c0 + 8), wget(w, COUT, CIN, r0,     c0 + 9),
        wget(w, COUT, CIN, r0 + 8, c0 + 8), wget(w, COUT, CIN, r0 + 8, c0 + 9)
    };
    uint32_t hi[4], lo[4];
    #pragma unroll
    for (int p = 0; p < 4; p++) {
        const float a = v[2 * p], b = v[2 * p + 1];
        __nv_bfloat162 hp = __floats2bfloat162_rn(a, b);
        const float ra = a - __bfloat162float(__low2bfloat16(hp));
        const float rb = b - __bfloat162float(__high2bfloat16(hp));
        __nv_bfloat162 lp = __floats2bfloat162_rn(ra, rb);
        hi[p] = *(uint32_t*)&hp;
        lo[p] = *(uint32_t*)&lp;
    }
    Ah[f] = make_uint4(hi[0], hi[1], hi[2], hi[3]);
    Al[f] = make_uint4(lo[0], lo[1], lo[2], lo[3]);
}

__global__ void prep_weights(const float* __restrict__ c1w,
                             const float* __restrict__ c2w,
                             const float* __restrict__ c3w)
{
    const int f = blockIdx.x * 256 + threadIdx.x;
    if (f < N1)                prep_frag(c1w, 200, 200, KS1, f,           g_A1h, g_A1l);
    else if (f < N1 + N2)      prep_frag(c2w, 100, 200, KS2, f - N1,      g_A2h, g_A2l);
    else if (f < N1 + N2 + N3) prep_frag(c3w, 100, 100, KS3, f - N1 - N2, g_A3h, g_A3l);
}

// ---------------------------------------------------------------------------
__global__ void __launch_bounds__(NT)
plan_cost_kernel(
    const float* __restrict__ trees, const int* __restrict__ indexes,
    const unsigned char* __restrict__ maskp,
    const float* __restrict__ c1b, const float* __restrict__ c2b,
    const float* __restrict__ c3b,
    const float* __restrict__ gw1, const float* __restrict__ gb1,
    const float* __restrict__ gw2, const float* __restrict__ gb2,
    const float* __restrict__ rw1, const float* __restrict__ rb1,
    const float* __restrict__ rw2, const float* __restrict__ rb2,
    const float* __restrict__ rw3, const float* __restrict__ rb3,
    float* __restrict__ out)
{
    const int b = blockIdx.x;
    const int t = threadIdx.x;
    int* idxs = (int*)&smem[S_IDX];

    {
        const int* isrc = indexes + (size_t)b * NIDX;
        for (int v = t; v < NIDX; v += NT) idxs[v] = isrc[v];
        const float* tb_ = trees + (size_t)b * 12800;
        for (int e = t; e < 12800; e += NT)
            split_store(tb_[e], bf_addr(e >> 6, e & 63));
        // zero pad channels 200..207 (layers 1 & 2 inputs, K=208)
        for (int e = t; e < 8 * 64; e += NT)
            zero_store(bf_addr(200 + (e >> 6), e & 63));
    }
    __syncthreads();

    conv_pass<TIL1, KS1, 200, true,  0 >(g_A1h, g_A1l, c1b, idxs);
    conv_pass<TIL2, KS2, 100, true,  12>(g_A2h, g_A2l, c2b, idxs);  // pad ch 100..111 for K=112
    conv_pass<TIL3, KS3, 100, false, 0 >(g_A3h, g_A3l, c3b, idxs);

    const float* H3 = &smem[XBUF];     // emb[n,f] = H3[f*64 + n]
    float* gates  = &smem[S_GATES];
    float* alphas = &smem[S_ALPHA];
    float* comb   = &smem[S_COMB];
    float* z1s    = &smem[S_Z1];
    float* z2s    = &smem[S_Z2];
    const int wid = t >> 5, lid = t & 31;

    // gate head
    for (int n = wid; n < 64; n += NW) {
        float acc1 = 0.f, acc2 = 0.f;
        const int h1 = lid;
        const int h2 = lid + 32;
        const float* w1p = gw1 + h1 * 100;
        const float* w2p = gw1 + h2 * 100;
        for (int f = 0; f < 100; f++) {
            const float e = H3[f * 64 + n];
            acc1 += e * __ldg(w1p + f);
            if (h2 < 50) acc2 += e * __ldg(w2p + f);
        }
        float contrib = fmaxf(acc1 + __ldg(gb1 + h1), 0.f) * __ldg(gw2 + h1);
        if (h2 < 50)
            contrib += fmaxf(acc2 + __ldg(gb1 + h2), 0.f) * __ldg(gw2 + h2);
        #pragma unroll
        for (int off = 16; off > 0; off >>= 1)
            contrib += __shfl_down_sync(0xffffffffu, contrib, off);
        if (lid == 0) {
            float gv = contrib + __ldg(gb2);
            if (maskp[(size_t)b * 64 + n]) gv = -INFINITY;
            gates[n] = gv;
        }
    }
    __syncthreads();

    // softmax over 64 nodes (warp 0)
    if (wid == 0) {
        const float v1 = gates[lid], v2 = gates[lid + 32];
        float m = fmaxf(v1, v2);
        #pragma unroll
        for (int off = 16; off > 0; off >>= 1)
            m = fmaxf(m, __shfl_xor_sync(0xffffffffu, m, off));
        const float e1 = expf(v1 - m), e2 = expf(v2 - m);
        float s = e1 + e2;
        #pragma unroll
        for (int off = 16; off > 0; off >>= 1)
            s += __shfl_xor_sync(0xffffffffu, s, off);
        const float invs = 1.f / s;
        alphas[lid] = e1 * invs;
        alphas[lid + 32] = e2 * invs;
    }
    __syncthreads();

    // pooled + root -> combined
    if (t < 100) {
        const float* row = H3 + t * 64;
        float acc = 0.f;
        #pragma unroll 4
        for (int n = 0; n < 64; n++) acc += alphas[n] * row[n];
        const float rootv = row[1];
        comb[t] = rootv;
        comb[100 + t] = acc;
        out[BATCH + (size_t)b * 200 + t] = rootv;
        out[BATCH + (size_t)b * 200 + 100 + t] = acc;
    }
    __syncthreads();

    // regressor MLP
    if (t < 128) {
        float acc = __ldg(rb1 + t);
        const float* wr = rw1 + t * 200;
        #pragma unroll 4
        for (int c = 0; c < 200; c++) acc += comb[c] * __ldg(wr + c);
        z1s[t] = fmaxf(acc, 0.f);
    }
    __syncthreads();
    if (t < 64) {
        float acc = __ldg(rb2 + t);
        const float* wr = rw2 + t * 128;
        #pragma unroll 4
        for (int c = 0; c < 128; c++) acc += z1s[c] * __ldg(wr + c);
        z2s[t] = fmaxf(acc, 0.f);
    }
    __syncthreads();
    if (wid == 0) {
        float acc = z2s[lid] * __ldg(rw3 + lid)
                  + z2s[lid + 32] * __ldg(rw3 + lid + 32);
        #pragma unroll
        for (int off = 16; off > 0; off >>= 1)
            acc += __shfl_down_sync(0xffffffffu, acc, off);
        if (lid == 0) out[b] = acc + __ldg(rb3);
    }
}

// ---------------------------------------------------------------------------
extern "C" void kernel_launch(void* const* d_in, const int* in_sizes, int n_in,
                              void* d_out, int out_size)
{
    (void)in_sizes; (void)n_in; (void)out_size;
    const size_t smem_bytes = (size_t)SMEM_FLOATS * sizeof(float);
    cudaFuncSetAttribute(plan_cost_kernel,
                         cudaFuncAttributeMaxDynamicSharedMemorySize,
                         (int)smem_bytes);

    prep_weights<<<(N1 + N2 + N3 + 255) / 256, 256>>>(
        (const float*)d_in[3], (const float*)d_in[5], (const float*)d_in[7]);

    plan_cost_kernel<<<BATCH, NT, smem_bytes>>>(
        (const float*)d_in[0],
        (const int*)d_in[1],
        (const unsigned char*)d_in[2],
        (const float*)d_in[4],
        (const float*)d_in[6],
        (const float*)d_in[8],
        (const float*)d_in[9],  (const float*)d_in[10],
        (const float*)d_in[11], (const float*)d_in[12],
        (const float*)d_in[13], (const float*)d_in[14],
        (const float*)d_in[15], (const float*)d_in[16],
        (const float*)d_in[17], (const float*)d_in[18],
        (float*)d_out);
}

// round 13
// speedup vs baseline: 2.3663x; 1.1160x over previous
#include <cuda_runtime.h>
#include <cuda_bf16.h>
#include <cstdint>
#include <math.h>

// ============================================================================
// PlanCostEstimatorFull — round 13
// bf16x3 m16n8k16 conv stack, restructured for 2 CTAs/SM:
//  - half-N warp tiles (16 acc regs), __launch_bounds__(512,2), regs<=64
//  - XBUF/H3 in __device__ global scratch (smem 173KB -> 82KB)
//  - chunk = 6 M-tiles (12 MMA warps, 2 per tile)
//  - packed bf16x2 split stores
// ============================================================================

#define BATCH 2048
#define NT    512
#define NW    16
#define NIDX  189
#define CHUNK 6

#define TIL1  38
#define KS1   13
#define TIL2  19
#define KS2   13
#define TIL3  19
#define KS3   7

#define N1 (TIL1*KS1*32)   // 15808
#define N2 (TIL2*KS2*32)   // 7904
#define N3 (TIL3*KS3*32)   // 4256

__device__ uint4 g_A1h[N1], g_A1l[N1];
__device__ uint4 g_A2h[N2], g_A2l[N2];
__device__ uint4 g_A3h[N3], g_A3l[N3];

__device__ float g_xbuf[(size_t)BATCH * 12800];   // pre-LN activations
__device__ float g_emb [(size_t)BATCH * 6400];    // layer-3 output (emb)

// smem word offsets
#define XF_HI   0        /* 6656 words (13 ksteps x 512) */
#define XF_LO   6656     /* 6656 words */
#define YCH     13312    /* 96 rows x 68 = 6528 words */
#define YSTR    68
#define S_IDX   19840    /* 192 ints */
#define S_RED   20032    /* 40 */
#define S_GATES 20072
#define S_ALPHA 20136
#define S_COMB  20200
#define S_Z1    20400
#define S_Z2    20528
#define SMEM_FLOATS 20592   /* 82368 B */

extern __shared__ float smem[];

// ---------------------------------------------------------------------------
// B-plane bf16 element address (identical to round 12 — validated layout).
// ---------------------------------------------------------------------------
__device__ __forceinline__ int bf_addr(int i, int m) {
    const int s  = i >> 4, kk = i & 15;
    const int t  = (kk >> 1) & 3, d = kk & 1, e = kk >> 3;
    const int g  = m & 7, j = m >> 3;
    const int l  = g * 4 + t;
    const int r  = j * 2 + e, c = r >> 2, w = r & 3;
    const int ph = (c + ((l >> 1) & 3)) & 3;
    return (s * 512 + l * 16 + ph * 4 + w) * 2 + d;
}

// packed split store: channels (2*i2, 2*i2+1) at node m -> one 32-bit word per plane
__device__ __forceinline__ void split_pair_store(float v0, float v1, int i2, int m) {
    const int word = bf_addr(2 * i2, m) >> 1;        // d=0 -> even
    __nv_bfloat162 hp = __floats2bfloat162_rn(v0, v1);
    const float r0 = v0 - __bfloat162float(__low2bfloat16(hp));
    const float r1 = v1 - __bfloat162float(__high2bfloat16(hp));
    __nv_bfloat162 lp = __floats2bfloat162_rn(r0, r1);
    ((uint32_t*)smem)[word]        = *(uint32_t*)&hp;
    ((uint32_t*)smem)[6656 + word] = *(uint32_t*)&lp;
}

#define MMAB(d, a, b0, b1)                                                    \
    asm volatile("mma.sync.aligned.m16n8k16.row.col.f32.bf16.bf16.f32 "       \
        "{%0,%1,%2,%3},{%4,%5,%6,%7},{%8,%9},{%0,%1,%2,%3};"                  \
        : "+f"(d[0]), "+f"(d[1]), "+f"(d[2]), "+f"(d[3])                      \
        : "r"((a).x), "r"((a).y), "r"((a).z), "r"((a).w), "r"(b0), "r"(b1))

// ---------------------------------------------------------------------------
// conv layer: MMA over CHUNK M-tiles per phase (2 half-N warps per tile),
// gather+bias -> gout (global), optional LN (stats in regs, LN pass re-splits
// from gout into the XF planes).
// ---------------------------------------------------------------------------
template<int TILES, int KS, int COUT, bool LN, int PADN>
__device__ __forceinline__ void conv_pass(
    const uint4* __restrict__ Ah, const uint4* __restrict__ Al,
    const float* __restrict__ bias, const int* __restrict__ idxs,
    float* __restrict__ gout)
{
    const int t = threadIdx.x;
    const int wid = t >> 5, lane = t & 31;
    const int gid = lane >> 2, tid4 = lane & 3;
    const int rot = (lane >> 1) & 3;
    const int mt = wid >> 1, half = wid & 1;
    const int ocA = (((2 * half)     + rot) & 3) << 2;
    const int ocB = (((2 * half + 1) + rot) & 3) << 2;

    float s1 = 0.f, s2 = 0.f;

    for (int tb = 0; tb < TILES; tb += CHUNK) {
        const int T = tb + mt;
        const bool act = (wid < 2 * CHUNK) && (T < TILES);

        if (act) {
            float acc[4][4];
            #pragma unroll
            for (int j = 0; j < 4; j++)
                #pragma unroll
                for (int p = 0; p < 4; p++) acc[j][p] = 0.f;

            const uint4* A0h = Ah + (size_t)T * KS * 32 + lane;
            const uint4* A0l = Al + (size_t)T * KS * 32 + lane;

            uint4 c0h = __ldg(A0h),      c0l = __ldg(A0l);
            uint4 c1h = __ldg(A0h + 32), c1l = __ldg(A0l + 32);

            #pragma unroll 1
            for (int s = 0; s < KS; s++) {
                const int sn = (s + 2 < KS) ? s + 2 : KS - 1;
                const uint4 nh = __ldg(A0h + sn * 32);
                const uint4 nl = __ldg(A0l + sn * 32);

                const float* bh = &smem[XF_HI + s * 512 + lane * 16];
                const float* bl = &smem[XF_LO + s * 512 + lane * 16];

                {   // hi phase: Ah*Bh + Al*Bh
                    const uint4 hA = *(const uint4*)(bh + ocA);
                    const uint4 hB = *(const uint4*)(bh + ocB);
                    MMAB(acc[0], c0h, hA.x, hA.y); MMAB(acc[0], c0l, hA.x, hA.y);
                    MMAB(acc[1], c0h, hA.z, hA.w); MMAB(acc[1], c0l, hA.z, hA.w);
                    MMAB(acc[2], c0h, hB.x, hB.y); MMAB(acc[2], c0l, hB.x, hB.y);
                    MMAB(acc[3], c0h, hB.z, hB.w); MMAB(acc[3], c0l, hB.z, hB.w);
                }
                {   // lo phase: Ah*Bl
                    const uint4 LA = *(const uint4*)(bl + ocA);
                    const uint4 LB = *(const uint4*)(bl + ocB);
                    MMAB(acc[0], c0h, LA.x, LA.y);
                    MMAB(acc[1], c0h, LA.z, LA.w);
                    MMAB(acc[2], c0h, LB.x, LB.y);
                    MMAB(acc[3], c0h, LB.z, LB.w);
                }

                c0h = c1h; c0l = c1l;
                c1h = nh;  c1l = nl;
            }

            // write D frags to Ych
            const int lr = (T - tb) * 16 + gid;
            float* y0 = &smem[YCH + lr * YSTR + 2 * tid4];
            float* y1 = y0 + 8 * YSTR;
            #pragma unroll
            for (int j = 0; j < 4; j++) {
                const int jj = half * 4 + j;
                *(float2*)(y0 + 8 * jj) = make_float2(acc[j][0], acc[j][1]);
                *(float2*)(y1 + 8 * jj) = make_float2(acc[j][2], acc[j][3]);
            }
        }
        __syncthreads();

        // gather + bias -> global scratch
        const int o0 = (tb * 16) / 3;
        const int no = (COUT - o0 < 32) ? (COUT - o0) : 32;
        for (int e = t; e < no * 64; e += NT) {
            const int ol = e >> 6;
            const int m  = e & 63;
            float v = 0.f;
            if (m != 0) {
                const int j3 = 3 * (m - 1);
                v = smem[YCH + (3 * ol    ) * YSTR + idxs[j3]]
                  + smem[YCH + (3 * ol + 1) * YSTR + idxs[j3 + 1]]
                  + smem[YCH + (3 * ol + 2) * YSTR + idxs[j3 + 2]]
                  + __ldg(bias + o0 + ol);
            }
            gout[(o0 + ol) * 64 + m] = v;
            if (LN) { s1 += v; s2 += v * v; }
        }
        __syncthreads();
    }

    if (LN) {
        #pragma unroll
        for (int off = 16; off > 0; off >>= 1) {
            s1 += __shfl_down_sync(0xffffffffu, s1, off);
            s2 += __shfl_down_sync(0xffffffffu, s2, off);
        }
        if (lane == 0) { smem[S_RED + wid] = s1; smem[S_RED + 16 + wid] = s2; }
        __syncthreads();
        if (t == 0) {
            float S1 = 0.f, S2 = 0.f;
            #pragma unroll
            for (int w = 0; w < NW; w++) { S1 += smem[S_RED + w]; S2 += smem[S_RED + 16 + w]; }
            const float n = (float)(COUT * 64);
            const float mu = S1 / n;
            float var = (S2 - S1 * mu) / (n - 1.f);
            var = fmaxf(var, 0.f);
            smem[S_RED + 32] = mu;
            smem[S_RED + 33] = 1.f / (sqrtf(var) + 1e-5f);
        }
        __syncthreads();
        const float mu = smem[S_RED + 32], inv = smem[S_RED + 33];
        // LN + relu + split (channel pairs) from global scratch -> XF planes
        for (int e = t; e < (COUT / 2) * 64; e += NT) {
            const int i2 = e >> 6, m = e & 63;
            const float v0 = fmaxf((gout[i2 * 128 + m]      - mu) * inv, 0.f);
            const float v1 = fmaxf((gout[i2 * 128 + 64 + m] - mu) * inv, 0.f);
            split_pair_store(v0, v1, i2, m);
        }
        if (PADN > 0) {
            for (int e = t; e < (PADN / 2) * 64; e += NT)
                split_pair_store(0.f, 0.f, COUT / 2 + (e >> 6), e & 63);
        }
        __syncthreads();
    }
}

// ---------------------------------------------------------------------------
// Prep: bf16 hi/lo A fragments (unchanged from round 12).
// ---------------------------------------------------------------------------
__device__ __forceinline__ float wget(const float* w, int COUT, int CIN, int r, int c) {
    if (r < 3 * COUT && c < CIN) {
        const int o = r / 3, k = r - o * 3;
        return w[(o * CIN + c) * 3 + k];
    }
    return 0.f;
}

__device__ __forceinline__ void prep_frag(const float* __restrict__ w,
    int COUT, int CIN, int KS, int f, uint4* __restrict__ Ah, uint4* __restrict__ Al)
{
    const int T = f / (KS * 32);
    const int rem = f - T * KS * 32;
    const int s = rem >> 5;
    const int l = rem & 31;
    const int g = l >> 2, t = l & 3;
    const int r0 = T * 16 + g;
    const int c0 = s * 16 + 2 * t;

    const float v[8] = {
        wget(w, COUT, CIN, r0,     c0),     wget(w, COUT, CIN, r0,     c0 + 1),
        wget(w, COUT, CIN, r0 + 8, c0),     wget(w, COUT, CIN, r0 + 8, c0 + 1),
        wget(w, COUT, CIN, r0,     c0 + 8), wget(w, COUT, CIN, r0,     c0 + 9),
        wget(w, COUT, CIN, r0 + 8, c0 + 8), wget(w, COUT, CIN, r0 + 8, c0 + 9)
    };
    uint32_t hi[4], lo[4];
    #pragma unroll
    for (int p = 0; p < 4; p++) {
        const float a = v[2 * p], b = v[2 * p + 1];
        __nv_bfloat162 hp = __floats2bfloat162_rn(a, b);
        const float ra = a - __bfloat162float(__low2bfloat16(hp));
        const float rb = b - __bfloat162float(__high2bfloat16(hp));
        __nv_bfloat162 lp = __floats2bfloat162_rn(ra, rb);
        hi[p] = *(uint32_t*)&hp;
        lo[p] = *(uint32_t*)&lp;
    }
    Ah[f] = make_uint4(hi[0], hi[1], hi[2], hi[3]);
    Al[f] = make_uint4(lo[0], lo[1], lo[2], lo[3]);
}

__global__ void prep_weights(const float* __restrict__ c1w,
                             const float* __restrict__ c2w,
                             const float* __restrict__ c3w)
{
    const int f = blockIdx.x * 256 + threadIdx.x;
    if (f < N1)                prep_frag(c1w, 200, 200, KS1, f,           g_A1h, g_A1l);
    else if (f < N1 + N2)      prep_frag(c2w, 100, 200, KS2, f - N1,      g_A2h, g_A2l);
    else if (f < N1 + N2 + N3) prep_frag(c3w, 100, 100, KS3, f - N1 - N2, g_A3h, g_A3l);
}

// ---------------------------------------------------------------------------
__global__ void __launch_bounds__(NT, 2)
plan_cost_kernel(
    const float* __restrict__ trees, const int* __restrict__ indexes,
    const unsigned char* __restrict__ maskp,
    const float* __restrict__ c1b, const float* __restrict__ c2b,
    const float* __restrict__ c3b,
    const float* __restrict__ gw1, const float* __restrict__ gb1,
    const float* __restrict__ gw2, const float* __restrict__ gb2,
    const float* __restrict__ rw1, const float* __restrict__ rb1,
    const float* __restrict__ rw2, const float* __restrict__ rb2,
    const float* __restrict__ rw3, const float* __restrict__ rb3,
    float* __restrict__ out)
{
    const int b = blockIdx.x;
    const int t = threadIdx.x;
    int* idxs = (int*)&smem[S_IDX];
    float* xb = g_xbuf + (size_t)b * 12800;
    float* eb = g_emb  + (size_t)b * 6400;

    // init: indexes + trees split (channel-pair packed) + pad ch 200..207
    {
        const int* isrc = indexes + (size_t)b * NIDX;
        for (int v = t; v < NIDX; v += NT) idxs[v] = isrc[v];
        const float* tb_ = trees + (size_t)b * 12800;
        for (int e = t; e < 100 * 64; e += NT) {
            const int i2 = e >> 6, m = e & 63;
            split_pair_store(tb_[i2 * 128 + m], tb_[i2 * 128 + 64 + m], i2, m);
        }
        for (int e = t; e < 4 * 64; e += NT)
            split_pair_store(0.f, 0.f, 100 + (e >> 6), e & 63);
    }
    __syncthreads();

    conv_pass<TIL1, KS1, 200, true,  0 >(g_A1h, g_A1l, c1b, idxs, xb);
    conv_pass<TIL2, KS2, 100, true,  12>(g_A2h, g_A2l, c2b, idxs, xb);
    conv_pass<TIL3, KS3, 100, false, 0 >(g_A3h, g_A3l, c3b, idxs, eb);

    // copy emb back to smem (XF region free after layer-3 MMA)
    for (int e = t; e < 6400; e += NT) smem[e] = eb[e];
    __syncthreads();

    const float* H3 = &smem[0];        // emb[n,f] = H3[f*64 + n]
    float* gates  = &smem[S_GATES];
    float* alphas = &smem[S_ALPHA];
    float* comb   = &smem[S_COMB];
    float* z1s    = &smem[S_Z1];
    float* z2s    = &smem[S_Z2];
    const int wid = t >> 5, lid = t & 31;

    // gate head
    for (int n = wid; n < 64; n += NW) {
        float acc1 = 0.f, acc2 = 0.f;
        const int h1 = lid;
        const int h2 = lid + 32;
        const float* w1p = gw1 + h1 * 100;
        const float* w2p = gw1 + h2 * 100;
        for (int f = 0; f < 100; f++) {
            const float e = H3[f * 64 + n];
            acc1 += e * __ldg(w1p + f);
            if (h2 < 50) acc2 += e * __ldg(w2p + f);
        }
        float contrib = fmaxf(acc1 + __ldg(gb1 + h1), 0.f) * __ldg(gw2 + h1);
        if (h2 < 50)
            contrib += fmaxf(acc2 + __ldg(gb1 + h2), 0.f) * __ldg(gw2 + h2);
        #pragma unroll
        for (int off = 16; off > 0; off >>= 1)
            contrib += __shfl_down_sync(0xffffffffu, contrib, off);
        if (lid == 0) {
            float gv = contrib + __ldg(gb2);
            if (maskp[(size_t)b * 64 + n]) gv = -INFINITY;
            gates[n] = gv;
        }
    }
    __syncthreads();

    // softmax over 64 nodes (warp 0)
    if (wid == 0) {
        const float v1 = gates[lid], v2 = gates[lid + 32];
        float m = fmaxf(v1, v2);
        #pragma unroll
        for (int off = 16; off > 0; off >>= 1)
            m = fmaxf(m, __shfl_xor_sync(0xffffffffu, m, off));
        const float e1 = expf(v1 - m), e2 = expf(v2 - m);
        float s = e1 + e2;
        #pragma unroll
        for (int off = 16; off > 0; off >>= 1)
            s += __shfl_xor_sync(0xffffffffu, s, off);
        const float invs = 1.f / s;
        alphas[lid] = e1 * invs;
        alphas[lid + 32] = e2 * invs;
    }
    __syncthreads();

    // pooled + root -> combined
    if (t < 100) {
        const float* row = H3 + t * 64;
        float acc = 0.f;
        #pragma unroll 4
        for (int n = 0; n < 64; n++) acc += alphas[n] * row[n];
        const float rootv = row[1];
        comb[t] = rootv;
        comb[100 + t] = acc;
        out[BATCH + (size_t)b * 200 + t] = rootv;
        out[BATCH + (size_t)b * 200 + 100 + t] = acc;
    }
    __syncthreads();

    // regressor MLP
    if (t < 128) {
        float acc = __ldg(rb1 + t);
        const float* wr = rw1 + t * 200;
        #pragma unroll 4
        for (int c = 0; c < 200; c++) acc += comb[c] * __ldg(wr + c);
        z1s[t] = fmaxf(acc, 0.f);
    }
    __syncthreads();
    if (t < 64) {
        float acc = __ldg(rb2 + t);
        const float* wr = rw2 + t * 128;
        #pragma unroll 4
        for (int c = 0; c < 128; c++) acc += z1s[c] * __ldg(wr + c);
        z2s[t] = fmaxf(acc, 0.f);
    }
    __syncthreads();
    if (wid == 0) {
        float acc = z2s[lid] * __ldg(rw3 + lid)
                  + z2s[lid + 32] * __ldg(rw3 + lid + 32);
        #pragma unroll
        for (int off = 16; off > 0; off >>= 1)
            acc += __shfl_down_sync(0xffffffffu, acc, off);
        if (lid == 0) out[b] = acc + __ldg(rb3);
    }
}

// ---------------------------------------------------------------------------
extern "C" void kernel_launch(void* const* d_in, const int* in_sizes, int n_in,
                              void* d_out, int out_size)
{
    (void)in_sizes; (void)n_in; (void)out_size;
    const size_t smem_bytes = (size_t)SMEM_FLOATS * sizeof(float);
    cudaFuncSetAttribute(plan_cost_kernel,
                         cudaFuncAttributeMaxDynamicSharedMemorySize,
                         (int)smem_bytes);

    prep_weights<<<(N1 + N2 + N3 + 255) / 256, 256>>>(
        (const float*)d_in[3], (const float*)d_in[5], (const float*)d_in[7]);

    plan_cost_kernel<<<BATCH, NT, smem_bytes>>>(
        (const float*)d_in[0],
        (const int*)d_in[1],
        (const unsigned char*)d_in[2],
        (const float*)d_in[4],
        (const float*)d_in[6],
        (const float*)d_in[8],
        (const float*)d_in[9],  (const float*)d_in[10],
        (const float*)d_in[11], (const float*)d_in[12],
        (const float*)d_in[13], (const float*)d_in[14],
        (const float*)d_in[15], (const float*)d_in[16],
        (const float*)d_in[17], (const float*)d_in[18],
        (float*)d_out);
}

// round 15
// speedup vs baseline: 2.3763x; 1.0042x over previous
#include <cuda_runtime.h>
#include <cuda_bf16.h>
#include <cstdint>
#include <math.h>

// ============================================================================
// PlanCostEstimatorFull — round 15 (round 14 + alignment fix)
// bf16x3 m16n8k16, 2 CTAs/SM + scatter-replay elimination:
//  - column-major gather: warp-uniform node (broadcast idx), YSTR=67 ->
//    conflict-free Ych reads (stride 201 = 9 mod 32, odd)
//  - D-fragment writes are SCALAR stores (YSTR is odd -> float2 would trap)
//  - scratch transposed: xb[m*COUT+o]; emb transposed -> conflict-free heads
// ============================================================================

#define BATCH 2048
#define NT    512
#define NW    16
#define NIDX  189
#define CHUNK 6

#define TIL1  38
#define KS1   13
#define TIL2  19
#define KS2   13
#define TIL3  19
#define KS3   7

#define N1 (TIL1*KS1*32)   // 15808
#define N2 (TIL2*KS2*32)   // 7904
#define N3 (TIL3*KS3*32)   // 4256

__device__ uint4 g_A1h[N1], g_A1l[N1];
__device__ uint4 g_A2h[N2], g_A2l[N2];
__device__ uint4 g_A3h[N3], g_A3l[N3];

__device__ float g_xbuf[(size_t)BATCH * 12800];   // pre-LN activations, [m][o]
__device__ float g_emb [(size_t)BATCH * 6400];    // layer-3 output, [m][o]

// smem word offsets
#define XF_HI   0        /* 6656 words (13 ksteps x 512) */
#define XF_LO   6656
#define YCH     13312    /* 96 rows x 67 = 6432 words */
#define YSTR    67
#define S_IDX   19744    /* 192 ints */
#define S_RED   19936    /* 40 */
#define S_GATES 19976
#define S_ALPHA 20040
#define S_COMB  20104
#define S_Z1    20304
#define S_Z2    20432
#define SMEM_FLOATS 20496   /* 81984 B */

extern __shared__ float smem[];

// ---------------------------------------------------------------------------
// B-plane bf16 element address (validated in r12/r13).
// ---------------------------------------------------------------------------
__device__ __forceinline__ int bf_addr(int i, int m) {
    const int s  = i >> 4, kk = i & 15;
    const int t  = (kk >> 1) & 3, d = kk & 1, e = kk >> 3;
    const int g  = m & 7, j = m >> 3;
    const int l  = g * 4 + t;
    const int r  = j * 2 + e, c = r >> 2, w = r & 3;
    const int ph = (c + ((l >> 1) & 3)) & 3;
    return (s * 512 + l * 16 + ph * 4 + w) * 2 + d;
}

// packed split store: channels (2*i2, 2*i2+1) at node m -> one word per plane
__device__ __forceinline__ void split_pair_store(float v0, float v1, int i2, int m) {
    const int word = bf_addr(2 * i2, m) >> 1;
    __nv_bfloat162 hp = __floats2bfloat162_rn(v0, v1);
    const float r0 = v0 - __bfloat162float(__low2bfloat16(hp));
    const float r1 = v1 - __bfloat162float(__high2bfloat16(hp));
    __nv_bfloat162 lp = __floats2bfloat162_rn(r0, r1);
    ((uint32_t*)smem)[word]        = *(uint32_t*)&hp;
    ((uint32_t*)smem)[6656 + word] = *(uint32_t*)&lp;
}

#define MMAB(d, a, b0, b1)                                                    \
    asm volatile("mma.sync.aligned.m16n8k16.row.col.f32.bf16.bf16.f32 "       \
        "{%0,%1,%2,%3},{%4,%5,%6,%7},{%8,%9},{%0,%1,%2,%3};"                  \
        : "+f"(d[0]), "+f"(d[1]), "+f"(d[2]), "+f"(d[3])                      \
        : "r"((a).x), "r"((a).y), "r"((a).z), "r"((a).w), "r"(b0), "r"(b1))

// ---------------------------------------------------------------------------
template<int TILES, int KS, int COUT, bool LN, int PADN>
__device__ __forceinline__ void conv_pass(
    const uint4* __restrict__ Ah, const uint4* __restrict__ Al,
    const float* __restrict__ bias, const int* __restrict__ idxs,
    float* __restrict__ gout)
{
    const int t = threadIdx.x;
    const int wid = t >> 5, lane = t & 31;
    const int gid = lane >> 2, tid4 = lane & 3;
    const int rot = (lane >> 1) & 3;
    const int mt = wid >> 1, half = wid & 1;
    const int ocA = (((2 * half)     + rot) & 3) << 2;
    const int ocB = (((2 * half + 1) + rot) & 3) << 2;

    float s1 = 0.f, s2 = 0.f;

    for (int tb = 0; tb < TILES; tb += CHUNK) {
        const int T = tb + mt;
        const bool act = (wid < 2 * CHUNK) && (T < TILES);

        if (act) {
            float acc[4][4];
            #pragma unroll
            for (int j = 0; j < 4; j++)
                #pragma unroll
                for (int p = 0; p < 4; p++) acc[j][p] = 0.f;

            const uint4* A0h = Ah + (size_t)T * KS * 32 + lane;
            const uint4* A0l = Al + (size_t)T * KS * 32 + lane;

            uint4 c0h = __ldg(A0h),      c0l = __ldg(A0l);
            uint4 c1h = __ldg(A0h + 32), c1l = __ldg(A0l + 32);

            #pragma unroll 1
            for (int s = 0; s < KS; s++) {
                const int sn = (s + 2 < KS) ? s + 2 : KS - 1;
                const uint4 nh = __ldg(A0h + sn * 32);
                const uint4 nl = __ldg(A0l + sn * 32);

                const float* bh = &smem[XF_HI + s * 512 + lane * 16];
                const float* bl = &smem[XF_LO + s * 512 + lane * 16];

                {   // hi phase: Ah*Bh + Al*Bh
                    const uint4 hA = *(const uint4*)(bh + ocA);
                    const uint4 hB = *(const uint4*)(bh + ocB);
                    MMAB(acc[0], c0h, hA.x, hA.y); MMAB(acc[0], c0l, hA.x, hA.y);
                    MMAB(acc[1], c0h, hA.z, hA.w); MMAB(acc[1], c0l, hA.z, hA.w);
                    MMAB(acc[2], c0h, hB.x, hB.y); MMAB(acc[2], c0l, hB.x, hB.y);
                    MMAB(acc[3], c0h, hB.z, hB.w); MMAB(acc[3], c0l, hB.z, hB.w);
                }
                {   // lo phase: Ah*Bl
                    const uint4 LA = *(const uint4*)(bl + ocA);
                    const uint4 LB = *(const uint4*)(bl + ocB);
                    MMAB(acc[0], c0h, LA.x, LA.y);
                    MMAB(acc[1], c0h, LA.z, LA.w);
                    MMAB(acc[2], c0h, LB.x, LB.y);
                    MMAB(acc[3], c0h, LB.z, LB.w);
                }

                c0h = c1h; c0l = c1l;
                c1h = nh;  c1l = nl;
            }

            // write D frags to Ych — SCALAR stores (YSTR odd => no float2)
            const int lr = (T - tb) * 16 + gid;
            float* y0 = &smem[YCH + lr * YSTR + 2 * tid4];
            float* y1 = y0 + 8 * YSTR;
            #pragma unroll
            for (int j = 0; j < 4; j++) {
                const int jj = half * 4 + j;
                y0[8 * jj]     = acc[j][0];
                y0[8 * jj + 1] = acc[j][1];
                y1[8 * jj]     = acc[j][2];
                y1[8 * jj + 1] = acc[j][3];
            }
        }
        __syncthreads();

        // column-major gather: warp-uniform node m, lanes sweep outputs.
        // no is always a power of two (32, 8 or 4).
        const int o0 = (tb * 16) / 3;
        const int no = (COUT - o0 < 32) ? (COUT - o0) : 32;
        const int nsh = (no == 32) ? 5 : ((no == 8) ? 3 : 2);
        for (int e = t; e < (no << 6); e += NT) {
            const int ol = e & (no - 1);
            const int m  = e >> nsh;
            float v = 0.f;
            if (m != 0) {
                const int j3 = 3 * (m - 1);
                v = smem[YCH + (3 * ol    ) * YSTR + idxs[j3]]
                  + smem[YCH + (3 * ol + 1) * YSTR + idxs[j3 + 1]]
                  + smem[YCH + (3 * ol + 2) * YSTR + idxs[j3 + 2]]
                  + __ldg(bias + o0 + ol);
            }
            gout[m * COUT + o0 + ol] = v;
            if (LN) { s1 += v; s2 += v * v; }
        }
        __syncthreads();
    }

    if (LN) {
        #pragma unroll
        for (int off = 16; off > 0; off >>= 1) {
            s1 += __shfl_down_sync(0xffffffffu, s1, off);
            s2 += __shfl_down_sync(0xffffffffu, s2, off);
        }
        if (lane == 0) { smem[S_RED + wid] = s1; smem[S_RED + 16 + wid] = s2; }
        __syncthreads();
        if (t == 0) {
            float S1 = 0.f, S2 = 0.f;
            #pragma unroll
            for (int w = 0; w < NW; w++) { S1 += smem[S_RED + w]; S2 += smem[S_RED + 16 + w]; }
            const float n = (float)(COUT * 64);
            const float mu = S1 / n;
            float var = (S2 - S1 * mu) / (n - 1.f);
            var = fmaxf(var, 0.f);
            smem[S_RED + 32] = mu;
            smem[S_RED + 33] = 1.f / (sqrtf(var) + 1e-5f);
        }
        __syncthreads();
        const float mu = smem[S_RED + 32], inv = smem[S_RED + 33];
        // LN + relu + split (channel pairs) from transposed scratch
        constexpr int NC2 = COUT / 2;
        for (int e = t; e < 64 * NC2; e += NT) {
            const int m = e / NC2, i2 = e - m * NC2;
            const float2 xv = *(const float2*)(gout + m * COUT + 2 * i2);
            const float v0 = fmaxf((xv.x - mu) * inv, 0.f);
            const float v1 = fmaxf((xv.y - mu) * inv, 0.f);
            split_pair_store(v0, v1, i2, m);
        }
        if (PADN > 0) {
            for (int e = t; e < (PADN / 2) * 64; e += NT)
                split_pair_store(0.f, 0.f, COUT / 2 + (e >> 6), e & 63);
        }
        __syncthreads();
    }
}

// ---------------------------------------------------------------------------
// Prep: bf16 hi/lo A fragments (unchanged).
// ---------------------------------------------------------------------------
__device__ __forceinline__ float wget(const float* w, int COUT, int CIN, int r, int c) {
    if (r < 3 * COUT && c < CIN) {
        const int o = r / 3, k = r - o * 3;
        return w[(o * CIN + c) * 3 + k];
    }
    return 0.f;
}

__device__ __forceinline__ void prep_frag(const float* __restrict__ w,
    int COUT, int CIN, int KS, int f, uint4* __restrict__ Ah, uint4* __restrict__ Al)
{
    const int T = f / (KS * 32);
    const int rem = f - T * KS * 32;
    const int s = rem >> 5;
    const int l = rem & 31;
    const int g = l >> 2, t = l & 3;
    const int r0 = T * 16 + g;
    const int c0 = s * 16 + 2 * t;

    const float v[8] = {
        wget(w, COUT, CIN, r0,     c0),     wget(w, COUT, CIN, r0,     c0 + 1),
        wget(w, COUT, CIN, r0 + 8, c0),     wget(w, COUT, CIN, r0 + 8, c0 + 1),
        wget(w, COUT, CIN, r0,     c0 + 8), wget(w, COUT, CIN, r0,     c0 + 9),
        wget(w, COUT, CIN, r0 + 8, c0 + 8), wget(w, COUT, CIN, r0 + 8, c0 + 9)
    };
    uint32_t hi[4], lo[4];
    #pragma unroll
    for (int p = 0; p < 4; p++) {
        const float a = v[2 * p], b = v[2 * p + 1];
        __nv_bfloat162 hp = __floats2bfloat162_rn(a, b);
        const float ra = a - __bfloat162float(__low2bfloat16(hp));
        const float rb = b - __bfloat162float(__high2bfloat16(hp));
        __nv_bfloat162 lp = __floats2bfloat162_rn(ra, rb);
        hi[p] = *(uint32_t*)&hp;
        lo[p] = *(uint32_t*)&lp;
    }
    Ah[f] = make_uint4(hi[0], hi[1], hi[2], hi[3]);
    Al[f] = make_uint4(lo[0], lo[1], lo[2], lo[3]);
}

__global__ void prep_weights(const float* __restrict__ c1w,
                             const float* __restrict__ c2w,
                             const float* __restrict__ c3w)
{
    const int f = blockIdx.x * 256 + threadIdx.x;
    if (f < N1)                prep_frag(c1w, 200, 200, KS1, f,           g_A1h, g_A1l);
    else if (f < N1 + N2)      prep_frag(c2w, 100, 200, KS2, f - N1,      g_A2h, g_A2l);
    else if (f < N1 + N2 + N3) prep_frag(c3w, 100, 100, KS3, f - N1 - N2, g_A3h, g_A3l);
}

// ---------------------------------------------------------------------------
__global__ void __launch_bounds__(NT, 2)
plan_cost_kernel(
    const float* __restrict__ trees, const int* __restrict__ indexes,
    const unsigned char* __restrict__ maskp,
    const float* __restrict__ c1b, const float* __restrict__ c2b,
    const float* __restrict__ c3b,
    const float* __restrict__ gw1, const float* __restrict__ gb1,
    const float* __restrict__ gw2, const float* __restrict__ gb2,
    const float* __restrict__ rw1, const float* __restrict__ rb1,
    const float* __restrict__ rw2, const float* __restrict__ rb2,
    const float* __restrict__ rw3, const float* __restrict__ rb3,
    float* __restrict__ out)
{
    const int b = blockIdx.x;
    const int t = threadIdx.x;
    int* idxs = (int*)&smem[S_IDX];
    float* xb = g_xbuf + (size_t)b * 12800;
    float* eb = g_emb  + (size_t)b * 6400;

    // init: indexes + trees split (channel-pair packed) + pad ch 200..207
    {
        const int* isrc = indexes + (size_t)b * NIDX;
        for (int v = t; v < NIDX; v += NT) idxs[v] = isrc[v];
        const float* tb_ = trees + (size_t)b * 12800;
        for (int e = t; e < 100 * 64; e += NT) {
            const int i2 = e >> 6, m = e & 63;
            split_pair_store(tb_[i2 * 128 + m], tb_[i2 * 128 + 64 + m], i2, m);
        }
        for (int e = t; e < 4 * 64; e += NT)
            split_pair_store(0.f, 0.f, 100 + (e >> 6), e & 63);
    }
    __syncthreads();

    conv_pass<TIL1, KS1, 200, true,  0 >(g_A1h, g_A1l, c1b, idxs, xb);
    conv_pass<TIL2, KS2, 100, true,  12>(g_A2h, g_A2l, c2b, idxs, xb);
    conv_pass<TIL3, KS3, 100, false, 0 >(g_A3h, g_A3l, c3b, idxs, eb);

    // copy transposed emb back to smem: H3t[n*100 + f]
    for (int e = t; e < 6400; e += NT) smem[e] = eb[e];
    __syncthreads();

    const float* H3t = &smem[0];       // emb[n,f] = H3t[n*100 + f]
    float* gates  = &smem[S_GATES];
    float* alphas = &smem[S_ALPHA];
    float* comb   = &smem[S_COMB];
    float* z1s    = &smem[S_Z1];
    float* z2s    = &smem[S_Z2];
    const int wid = t >> 5, lid = t & 31;

    // gate head (fixed n per warp -> broadcast H3t reads)
    for (int n = wid; n < 64; n += NW) {
        float acc1 = 0.f, acc2 = 0.f;
        const int h1 = lid;
        const int h2 = lid + 32;
        const float* w1p = gw1 + h1 * 100;
        const float* w2p = gw1 + h2 * 100;
        const float* er = H3t + n * 100;
        for (int f = 0; f < 100; f++) {
            const float e = er[f];
            acc1 += e * __ldg(w1p + f);
            if (h2 < 50) acc2 += e * __ldg(w2p + f);
        }
        float contrib = fmaxf(acc1 + __ldg(gb1 + h1), 0.f) * __ldg(gw2 + h1);
        if (h2 < 50)
            contrib += fmaxf(acc2 + __ldg(gb1 + h2), 0.f) * __ldg(gw2 + h2);
        #pragma unroll
        for (int off = 16; off > 0; off >>= 1)
            contrib += __shfl_down_sync(0xffffffffu, contrib, off);
        if (lid == 0) {
            float gv = contrib + __ldg(gb2);
            if (maskp[(size_t)b * 64 + n]) gv = -INFINITY;
            gates[n] = gv;
        }
    }
    __syncthreads();

    // softmax over 64 nodes (warp 0)
    if (wid == 0) {
        const float v1 = gates[lid], v2 = gates[lid + 32];
        float m = fmaxf(v1, v2);
        #pragma unroll
        for (int off = 16; off > 0; off >>= 1)
            m = fmaxf(m, __shfl_xor_sync(0xffffffffu, m, off));
        const float e1 = expf(v1 - m), e2 = expf(v2 - m);
        float s = e1 + e2;
        #pragma unroll
        for (int off = 16; off > 0; off >>= 1)
            s += __shfl_xor_sync(0xffffffffu, s, off);
        const float invs = 1.f / s;
        alphas[lid] = e1 * invs;
        alphas[lid + 32] = e2 * invs;
    }
    __syncthreads();

    // pooled + root -> combined (lane-stride-1 H3t reads, conflict-free)
    if (t < 100) {
        float acc = 0.f;
        #pragma unroll 4
        for (int n = 0; n < 64; n++) acc += alphas[n] * H3t[n * 100 + t];
        const float rootv = H3t[100 + t];     // node n=1
        comb[t] = rootv;
        comb[100 + t] = acc;
        out[BATCH + (size_t)b * 200 + t] = rootv;
        out[BATCH + (size_t)b * 200 + 100 + t] = acc;
    }
    __syncthreads();

    // regressor MLP
    if (t < 128) {
        float acc = __ldg(rb1 + t);
        const float* wr = rw1 + t * 200;
        #pragma unroll 4
        for (int c = 0; c < 200; c++) acc += comb[c] * __ldg(wr + c);
        z1s[t] = fmaxf(acc, 0.f);
    }
    __syncthreads();
    if (t < 64) {
        float acc = __ldg(rb2 + t);
        const float* wr = rw2 + t * 128;
        #pragma unroll 4
        for (int c = 0; c < 128; c++) acc += z1s[c] * __ldg(wr + c);
        z2s[t] = fmaxf(acc, 0.f);
    }
    __syncthreads();
    if (wid == 0) {
        float acc = z2s[lid] * __ldg(rw3 + lid)
                  + z2s[lid + 32] * __ldg(rw3 + lid + 32);
        #pragma unroll
        for (int off = 16; off > 0; off >>= 1)
            acc += __shfl_down_sync(0xffffffffu, acc, off);
        if (lid == 0) out[b] = acc + __ldg(rb3);
    }
}

// ---------------------------------------------------------------------------
extern "C" void kernel_launch(void* const* d_in, const int* in_sizes, int n_in,
                              void* d_out, int out_size)
{
    (void)in_sizes; (void)n_in; (void)out_size;
    const size_t smem_bytes = (size_t)SMEM_FLOATS * sizeof(float);
    cudaFuncSetAttribute(plan_cost_kernel,
                         cudaFuncAttributeMaxDynamicSharedMemorySize,
                         (int)smem_bytes);

    prep_weights<<<(N1 + N2 + N3 + 255) / 256, 256>>>(
        (const float*)d_in[3], (const float*)d_in[5], (const float*)d_in[7]);

    plan_cost_kernel<<<BATCH, NT, smem_bytes>>>(
        (const float*)d_in[0],
        (const int*)d_in[1],
        (const unsigned char*)d_in[2],
        (const float*)d_in[4],
        (const float*)d_in[6],
        (const float*)d_in[8],
        (const float*)d_in[9],  (const float*)d_in[10],
        (const float*)d_in[11], (const float*)d_in[12],
        (const float*)d_in[13], (const float*)d_in[14],
        (const float*)d_in[15], (const float*)d_in[16],
        (const float*)d_in[17], (const float*)d_in[18],
        (float*)d_out);
}